// round 7
// baseline (speedup 1.0000x reference)
#include <cuda_runtime.h>
#include <cuda_bf16.h>
#include <cstdint>

#define B_  4
#define L_  2048
#define H_  512
#define NH  8
#define D_  64
#define GP  68            // fp32 staging pitch (floats)

// ---------------- scratch (static device globals; no allocation) ----------------
__device__ __nv_bfloat16 g_Qbf[B_*NH*L_*D_];   // (b,h,l,d), scaled by 0.125*log2e
__device__ __nv_bfloat16 g_Kbf[B_*NH*L_*D_];
__device__ __nv_bfloat16 g_Wpbf[4096*D_];      // rows >= 4095 zero-padded
__device__ float g_V[B_*NH*L_*D_];             // fp32 head layout
__device__ float g_Diag[B_*NH*L_];             // softmax diagonal values

__device__ __forceinline__ float fast_exp2(float x) {
    float y; asm("ex2.approx.f32 %0, %1;" : "=f"(y) : "f"(x)); return y;
}
__device__ __forceinline__ void mma16816(float* c, uint32_t a0, uint32_t a1,
                                         uint32_t a2, uint32_t a3,
                                         uint32_t b0, uint32_t b1) {
    asm volatile(
        "mma.sync.aligned.m16n8k16.row.col.f32.bf16.bf16.f32 "
        "{%0,%1,%2,%3}, {%4,%5,%6,%7}, {%8,%9}, {%0,%1,%2,%3};"
        : "+f"(c[0]), "+f"(c[1]), "+f"(c[2]), "+f"(c[3])
        : "r"(a0), "r"(a1), "r"(a2), "r"(a3), "r"(b0), "r"(b1));
}
__device__ __forceinline__ uint32_t smem_u32(const void* p) {
    uint32_t a;
    asm("{ .reg .u64 t; cvta.to.shared.u64 t, %1; cvt.u32.u64 %0, t; }" : "=r"(a) : "l"(p));
    return a;
}
__device__ __forceinline__ void cp16(uint32_t s, const void* g) {
    asm volatile("cp.async.cg.shared.global [%0], [%1], 16;" :: "r"(s), "l"(g));
}
__device__ __forceinline__ void cp4(uint32_t s, const void* g) {
    asm volatile("cp.async.ca.shared.global [%0], [%1], 4;" :: "r"(s), "l"(g));
}
#define CP_COMMIT() asm volatile("cp.async.commit_group;" ::: "memory")

// load two fp32 from smem, convert to packed bf16x2 (lo = p[0], hi = p[1])
__device__ __forceinline__ uint32_t ld_cvt(const float* p) {
    float2 v = *(const float2*)p;
    __nv_bfloat162 h = __halves2bfloat162(__float2bfloat16(v.x), __float2bfloat16(v.y));
    return *reinterpret_cast<uint32_t*>(&h);
}
__device__ __forceinline__ uint32_t ld_cvt_s(const float* p, float s) {
    float2 v = *(const float2*)p;
    __nv_bfloat162 h = __halves2bfloat162(__float2bfloat16(v.x*s), __float2bfloat16(v.y*s));
    return *reinterpret_cast<uint32_t*>(&h);
}

// ---------------- Kernel 1: QKV projections, pipelined bf16 HMMA ----------------
// 512 thr, 128x128 tile, cp.async double-buffered fp32 staging, cvt in fragment path.
#define QKV_SMEM (4 * 128 * GP * 4)      // 139264 B

__global__ __launch_bounds__(512, 1)
void gemm_qkv_bf16(const float* __restrict__ q_in, const float* __restrict__ k_in,
                   const float* __restrict__ v_in,
                   const float* __restrict__ Wq, const float* __restrict__ bq,
                   const float* __restrict__ Wk, const float* __restrict__ bk,
                   const float* __restrict__ Wv, const float* __restrict__ bv)
{
    extern __shared__ float gsm[];
    float* Abuf[2] = { gsm,            gsm + 2*128*GP };
    float* Wbuf[2] = { gsm + 128*GP,   gsm + 3*128*GP };

    int mode = blockIdx.z;
    const float *A, *W, *bias;
    if (mode == 0)      { A = q_in; W = Wq; bias = bq; }
    else if (mode == 1) { A = k_in; W = Wk; bias = bk; }
    else                { A = v_in; W = Wv; bias = bv; }

    const int m0 = blockIdx.y * 128, n0 = blockIdx.x * 128;
    const int tid = threadIdx.x, lane = tid & 31, w = tid >> 5;
    const int wr = w >> 2, wc = w & 3;
    const int g = lane >> 2, qd = lane & 3;

    auto cp_chunk = [&](int buf, int k0) {
        const float* Ag = A + (size_t)m0 * H_ + k0;
        const float* Wg = W + (size_t)n0 * H_ + k0;
        #pragma unroll
        for (int i = 0; i < 4; i++) {
            int line = tid + i*512;            // 0..2047
            int r = line >> 4, c = (line & 15) * 4;
            cp16(smem_u32(Abuf[buf] + r*GP + c), Ag + (size_t)r * H_ + c);
            cp16(smem_u32(Wbuf[buf] + r*GP + c), Wg + (size_t)r * H_ + c);
        }
    };

    float acc[2][4][4] = {};

    cp_chunk(0, 0);
    CP_COMMIT();

    for (int kc = 0; kc < 8; kc++) {
        int cur = kc & 1;
        if (kc < 7) { cp_chunk(cur ^ 1, (kc+1)*64); CP_COMMIT(); }
        if (kc < 7) asm volatile("cp.async.wait_group 1;" ::: "memory");
        else        asm volatile("cp.async.wait_group 0;" ::: "memory");
        __syncthreads();

        const float* Af = Abuf[cur];
        const float* Wf = Wbuf[cur];
        #pragma unroll
        for (int kk = 0; kk < 4; kk++) {
            uint32_t a[2][4];
            #pragma unroll
            for (int mf = 0; mf < 2; mf++) {
                const float* ap = Af + (wr*32 + mf*16 + g)*GP + kk*16 + qd*2;
                a[mf][0] = ld_cvt(ap);
                a[mf][1] = ld_cvt(ap + 8*GP);
                a[mf][2] = ld_cvt(ap + 8);
                a[mf][3] = ld_cvt(ap + 8*GP + 8);
            }
            #pragma unroll
            for (int nf = 0; nf < 4; nf++) {
                const float* bp = Wf + (wc*32 + nf*8 + g)*GP + kk*16 + qd*2;
                uint32_t b0 = ld_cvt(bp);
                uint32_t b1 = ld_cvt(bp + 8);
                mma16816(acc[0][nf], a[0][0],a[0][1],a[0][2],a[0][3], b0,b1);
                mma16816(acc[1][nf], a[1][0],a[1][1],a[1][2],a[1][3], b0,b1);
            }
        }
        __syncthreads();
    }

    const float qs = 0.125f * 1.4426950408889634f;
    #pragma unroll
    for (int mf = 0; mf < 2; mf++) {
        int rg = m0 + wr*32 + mf*16 + g;
        int b = rg >> 11, l = rg & (L_ - 1);
        #pragma unroll
        for (int nf = 0; nf < 4; nf++) {
            int n = n0 + wc*32 + nf*8 + qd*2;
            int h = n >> 6, d = n & 63;
            float b0 = bias[n], b1 = bias[n+1];
            float v00 = acc[mf][nf][0] + b0, v01 = acc[mf][nf][1] + b1;
            float v10 = acc[mf][nf][2] + b0, v11 = acc[mf][nf][3] + b1;
            size_t o0 = ((size_t)(b*NH + h) * L_ + l) * D_ + d;
            size_t o1 = o0 + 8*D_;
            if (mode == 0) {
                *(__nv_bfloat162*)(g_Qbf + o0) =
                    __halves2bfloat162(__float2bfloat16(v00*qs), __float2bfloat16(v01*qs));
                *(__nv_bfloat162*)(g_Qbf + o1) =
                    __halves2bfloat162(__float2bfloat16(v10*qs), __float2bfloat16(v11*qs));
            } else if (mode == 1) {
                *(__nv_bfloat162*)(g_Kbf + o0) =
                    __halves2bfloat162(__float2bfloat16(v00), __float2bfloat16(v01));
                *(__nv_bfloat162*)(g_Kbf + o1) =
                    __halves2bfloat162(__float2bfloat16(v10), __float2bfloat16(v11));
            } else {
                *(float2*)(g_V + o0) = make_float2(v00, v01);
                *(float2*)(g_V + o1) = make_float2(v10, v11);
            }
        }
    }
}

// ---------------- Kernel 1b: convert Wp to padded bf16 --------------------------
__global__ __launch_bounds__(256)
void wp_convert_kernel(const float* __restrict__ Wp)
{
    int idx = blockIdx.x * 256 + threadIdx.x;   // < 4096*64
    int r = idx >> 6;
    g_Wpbf[idx] = __float2bfloat16(r < 2*L_ - 1 ? Wp[idx] : 0.f);
}

// ---------------- Kernel 2: HMMA score pass, rolling-P ring, async pipeline -----
#define PSP 520
#define AOFF_KS0 18432
#define AOFF_KS1 36864
#define AOFF_WS0 55296
#define AOFF_WS1 73728
#define AOFF_PS  92160
#define AOFF_WB  225280
#define AOFF_SD  226304
#define AOFF_RED 226816
#define ATT_SMEM 228864

__global__ __launch_bounds__(512, 1)
void attn_mma_kernel(const float* __restrict__ Wpb)
{
    extern __shared__ char smc[];
    __nv_bfloat16* Qs  = (__nv_bfloat16*)(smc);
    __nv_bfloat16* Psm = (__nv_bfloat16*)(smc + AOFF_PS);
    float* wbn   = (float*)(smc + AOFF_WB);    // [2][128]
    float* sdArr = (float*)(smc + AOFF_SD);
    float* red   = (float*)(smc + AOFF_RED);   // [4][128]

    const int tid = threadIdx.x;
    const int lane = tid & 31, w = tid >> 5;
    const int wr = w >> 2, wc = w & 3;
    const int g = lane >> 2, qd = lane & 3;
    const int bh = blockIdx.y, it = blockIdx.x;
    const int i0 = it * 128;
    const int rbase0 = 1920 - 128*it;

    const uint32_t ks_s[2] = { smem_u32(smc + AOFF_KS0), smem_u32(smc + AOFF_KS1) };
    const uint32_t ws_s[2] = { smem_u32(smc + AOFF_WS0), smem_u32(smc + AOFF_WS1) };

    auto cp_tile = [&](uint32_t sbase, const __nv_bfloat16* gsrc) {
        const uint4* g4 = (const uint4*)gsrc;
        #pragma unroll
        for (int t = tid; t < 1024; t += 512) {
            int r = t >> 3, c = t & 7;
            cp16(sbase + (r*72 + c*8)*2, g4 + t);
        }
    };

    {
        const uint4* Qg4 = (const uint4*)(g_Qbf + ((size_t)bh * L_ + i0) * D_);
        for (int t = tid; t < 1024; t += 512) {
            int r = t >> 3, c = t & 7;
            *(uint4*)(Qs + r*72 + c*8) = Qg4[t];
        }
    }
    cp_tile(ks_s[0], g_Kbf + (size_t)bh * L_ * D_);
    cp_tile(ws_s[1], g_Wpbf + (size_t)rbase0 * D_);
    cp_tile(ws_s[0], g_Wpbf + (size_t)(rbase0 + 128) * D_);
    CP_COMMIT();
    if (tid < 128) {
        wbn[128 + tid] = Wpb[rbase0 + tid] * 1.4426950408889634f;
        wbn[tid]       = Wpb[rbase0 + 128 + tid] * 1.4426950408889634f;
    }
    asm volatile("cp.async.wait_group 0;" ::: "memory");
    __syncthreads();

    auto pblock = [&](const __nv_bfloat16* Ws, const float* wb, int slot) {
        float accP[2][4][4] = {};
        #pragma unroll
        for (int kk = 0; kk < 4; kk++) {
            uint32_t a[2][4];
            #pragma unroll
            for (int mf = 0; mf < 2; mf++) {
                const __nv_bfloat16* qp = Qs + (wr*32 + mf*16 + g)*72 + kk*16 + qd*2;
                a[mf][0] = *(const uint32_t*)(qp);
                a[mf][1] = *(const uint32_t*)(qp + 8*72);
                a[mf][2] = *(const uint32_t*)(qp + 8);
                a[mf][3] = *(const uint32_t*)(qp + 8*72 + 8);
            }
            #pragma unroll
            for (int nf = 0; nf < 4; nf++) {
                const __nv_bfloat16* bp = Ws + (wc*32 + nf*8 + g)*72 + kk*16 + qd*2;
                uint32_t b0 = *(const uint32_t*)(bp);
                uint32_t b1 = *(const uint32_t*)(bp + 8);
                mma16816(accP[0][nf], a[0][0],a[0][1],a[0][2],a[0][3], b0,b1);
                mma16816(accP[1][nf], a[1][0],a[1][1],a[1][2],a[1][3], b0,b1);
            }
        }
        int pb = slot * 128;
        #pragma unroll
        for (int mf = 0; mf < 2; mf++) {
            int r0 = wr*32 + mf*16 + g, r1 = r0 + 8;
            #pragma unroll
            for (int nf = 0; nf < 4; nf++) {
                int c = wc*32 + nf*8 + qd*2;
                float b0 = wb[c], b1 = wb[c+1];
                __nv_bfloat16 v00 = __float2bfloat16(accP[mf][nf][0] + b0);
                __nv_bfloat16 v01 = __float2bfloat16(accP[mf][nf][1] + b1);
                __nv_bfloat16 v10 = __float2bfloat16(accP[mf][nf][2] + b0);
                __nv_bfloat16 v11 = __float2bfloat16(accP[mf][nf][3] + b1);
                Psm[r0*PSP + pb + c]     = v00;
                Psm[r0*PSP + pb + c + 1] = v01;
                Psm[r1*PSP + pb + c]     = v10;
                Psm[r1*PSP + pb + c + 1] = v11;
                if (slot == 0) {
                    Psm[r0*PSP + 384 + c]     = v00;
                    Psm[r0*PSP + 384 + c + 1] = v01;
                    Psm[r1*PSP + 384 + c]     = v10;
                    Psm[r1*PSP + 384 + c + 1] = v11;
                }
            }
        }
    };

    int sigma = (rbase0 >> 7) % 3;
    pblock((const __nv_bfloat16*)(smc + AOFF_WS1), wbn + 128, sigma);

    float rs[4] = {0.f, 0.f, 0.f, 0.f};

    for (int jt = 0; jt < L_/128; jt++) {
        int cur = jt & 1, nxt = cur ^ 1;
        int s_w = sigma + 1; if (s_w == 3) s_w = 0;
        __syncthreads();

        if (jt < 15) {
            cp_tile(ks_s[nxt], g_Kbf + ((size_t)bh * L_ + (jt+1)*128) * D_);
            cp_tile(ws_s[nxt], g_Wpbf + (size_t)(rbase0 + (jt+2)*128) * D_);
            CP_COMMIT();
            if (tid < 128) {
                int idx = rbase0 + (jt+2)*128 + tid;
                wbn[nxt*128 + tid] = (idx < 2*L_ - 1)
                                   ? Wpb[idx] * 1.4426950408889634f : 0.f;
            }
            asm volatile("cp.async.wait_group 1;" ::: "memory");
        } else {
            asm volatile("cp.async.wait_group 0;" ::: "memory");
        }
        __syncthreads();

        const __nv_bfloat16* Ks = (const __nv_bfloat16*)(smc + (cur ? AOFF_KS1 : AOFF_KS0));
        const __nv_bfloat16* Ws = (const __nv_bfloat16*)(smc + (cur ? AOFF_WS1 : AOFF_WS0));

        pblock(Ws, wbn + cur*128, s_w);

        float accS[2][4][4] = {};
        #pragma unroll
        for (int kk = 0; kk < 4; kk++) {
            uint32_t a[2][4];
            #pragma unroll
            for (int mf = 0; mf < 2; mf++) {
                const __nv_bfloat16* qp = Qs + (wr*32 + mf*16 + g)*72 + kk*16 + qd*2;
                a[mf][0] = *(const uint32_t*)(qp);
                a[mf][1] = *(const uint32_t*)(qp + 8*72);
                a[mf][2] = *(const uint32_t*)(qp + 8);
                a[mf][3] = *(const uint32_t*)(qp + 8*72 + 8);
            }
            #pragma unroll
            for (int nf = 0; nf < 4; nf++) {
                const __nv_bfloat16* bp = Ks + (wc*32 + nf*8 + g)*72 + kk*16 + qd*2;
                uint32_t b0 = *(const uint32_t*)(bp);
                uint32_t b1 = *(const uint32_t*)(bp + 8);
                mma16816(accS[0][nf], a[0][0],a[0][1],a[0][2],a[0][3], b0,b1);
                mma16816(accS[1][nf], a[1][0],a[1][1],a[1][2],a[1][3], b0,b1);
            }
        }
        __syncthreads();

        bool dt = (jt == it);
        int off = sigma*128 + 127;
        #pragma unroll
        for (int mf = 0; mf < 2; mf++) {
            int r0 = wr*32 + mf*16 + g, r1 = r0 + 8;
            const __nv_bfloat16* base0 = Psm + r0*PSP + off - r0;
            const __nv_bfloat16* base1 = Psm + r1*PSP + off - r1;
            #pragma unroll
            for (int nf = 0; nf < 4; nf++) {
                int j = wc*32 + nf*8 + qd*2;
                float t00 = accS[mf][nf][0] + __bfloat162float(base0[j]);
                float t01 = accS[mf][nf][1] + __bfloat162float(base0[j+1]);
                float t10 = accS[mf][nf][2] + __bfloat162float(base1[j]);
                float t11 = accS[mf][nf][3] + __bfloat162float(base1[j+1]);
                rs[mf*2+0] += fast_exp2(t00) + fast_exp2(t01);
                rs[mf*2+1] += fast_exp2(t10) + fast_exp2(t11);
                if (dt) {
                    if (j == r0)          sdArr[r0] = t00;
                    else if (j + 1 == r0) sdArr[r0] = t01;
                    if (j == r1)          sdArr[r1] = t10;
                    else if (j + 1 == r1) sdArr[r1] = t11;
                }
            }
        }
        sigma = s_w;
    }

    #pragma unroll
    for (int k = 0; k < 4; k++) {
        rs[k] += __shfl_xor_sync(0xffffffffu, rs[k], 1);
        rs[k] += __shfl_xor_sync(0xffffffffu, rs[k], 2);
    }
    if (qd == 0) {
        int base = wc*128 + wr*32 + g;
        red[base]      = rs[0];
        red[base + 8]  = rs[1];
        red[base + 16] = rs[2];
        red[base + 24] = rs[3];
    }
    __syncthreads();
    if (tid < 128) {
        float r = red[tid] + red[128 + tid] + red[256 + tid] + red[384 + tid];
        g_Diag[(size_t)bh * L_ + i0 + tid] = fast_exp2(sdArr[tid]) / r;
    }
}

// ---------------- Kernel 3: O projection, pipelined, fused diag*V ---------------
#define OUT_SMEM (4 * 128 * GP * 4 + 2 * 128 * 4)   // +dgs[2][128]

__global__ __launch_bounds__(512, 1)
void gemm_out_bf16(const float* __restrict__ Wo, const float* __restrict__ bo,
                   float* __restrict__ out)
{
    extern __shared__ float gsm[];
    float* Abuf[2] = { gsm,            gsm + 2*128*GP };
    float* Wbuf[2] = { gsm + 128*GP,   gsm + 3*128*GP };
    float* dgs     = gsm + 4*128*GP;                  // [2][128]

    const int m0 = blockIdx.y * 128, n0 = blockIdx.x * 128;
    const int tid = threadIdx.x, lane = tid & 31, w = tid >> 5;
    const int wr = w >> 2, wc = w & 3;
    const int g = lane >> 2, qd = lane & 3;

    const int b = m0 >> 11, l0 = m0 & (L_ - 1);

    auto cp_chunk = [&](int buf, int h) {
        const float* Ag = g_V + ((size_t)(b*NH + h) * L_ + l0) * D_;
        const float* Wg = Wo + (size_t)n0 * H_ + h*64;
        #pragma unroll
        for (int i = 0; i < 4; i++) {
            int line = tid + i*512;
            int r = line >> 4, c = (line & 15) * 4;
            cp16(smem_u32(Abuf[buf] + r*GP + c), Ag + (size_t)r * D_ + c);
            cp16(smem_u32(Wbuf[buf] + r*GP + c), Wg + (size_t)r * H_ + c);
        }
        if (tid < 128)
            cp4(smem_u32(dgs + buf*128 + tid),
                g_Diag + (size_t)(b*NH + h) * L_ + l0 + tid);
    };

    float acc[2][4][4] = {};

    cp_chunk(0, 0);
    CP_COMMIT();

    for (int kc = 0; kc < 8; kc++) {
        int cur = kc & 1;
        if (kc < 7) { cp_chunk(cur ^ 1, kc + 1); CP_COMMIT(); }
        if (kc < 7) asm volatile("cp.async.wait_group 1;" ::: "memory");
        else        asm volatile("cp.async.wait_group 0;" ::: "memory");
        __syncthreads();

        const float* Af = Abuf[cur];
        const float* Wf = Wbuf[cur];
        const float* dg = dgs + cur*128;
        #pragma unroll
        for (int kk = 0; kk < 4; kk++) {
            uint32_t a[2][4];
            #pragma unroll
            for (int mf = 0; mf < 2; mf++) {
                int r0 = wr*32 + mf*16 + g;
                float d0 = dg[r0], d1 = dg[r0 + 8];
                const float* ap = Af + r0*GP + kk*16 + qd*2;
                a[mf][0] = ld_cvt_s(ap,            d0);
                a[mf][1] = ld_cvt_s(ap + 8*GP,     d1);
                a[mf][2] = ld_cvt_s(ap + 8,        d0);
                a[mf][3] = ld_cvt_s(ap + 8*GP + 8, d1);
            }
            #pragma unroll
            for (int nf = 0; nf < 4; nf++) {
                const float* bp = Wf + (wc*32 + nf*8 + g)*GP + kk*16 + qd*2;
                uint32_t b0 = ld_cvt(bp);
                uint32_t b1 = ld_cvt(bp + 8);
                mma16816(acc[0][nf], a[0][0],a[0][1],a[0][2],a[0][3], b0,b1);
                mma16816(acc[1][nf], a[1][0],a[1][1],a[1][2],a[1][3], b0,b1);
            }
        }
        __syncthreads();
    }

    #pragma unroll
    for (int mf = 0; mf < 2; mf++) {
        int rg = m0 + wr*32 + mf*16 + g;
        #pragma unroll
        for (int nf = 0; nf < 4; nf++) {
            int n = n0 + wc*32 + nf*8 + qd*2;
            float b0 = bo[n], b1 = bo[n+1];
            *(float2*)(out + (size_t)rg * H_ + n) =
                make_float2(acc[mf][nf][0] + b0, acc[mf][nf][1] + b1);
            *(float2*)(out + (size_t)(rg + 8) * H_ + n) =
                make_float2(acc[mf][nf][2] + b0, acc[mf][nf][3] + b1);
        }
    }
}

// ---------------- launch --------------------------------------------------------
extern "C" void kernel_launch(void* const* d_in, const int* in_sizes, int n_in,
                              void* d_out, int out_size)
{
    const float* q_in = (const float*)d_in[0];
    const float* k_in = (const float*)d_in[1];
    const float* v_in = (const float*)d_in[2];
    const float* Wq_w = (const float*)d_in[3];
    const float* Wq_b = (const float*)d_in[4];
    const float* Wk_w = (const float*)d_in[5];
    const float* Wk_b = (const float*)d_in[6];
    const float* Wv_w = (const float*)d_in[7];
    const float* Wv_b = (const float*)d_in[8];
    const float* Wo_w = (const float*)d_in[9];
    const float* Wo_b = (const float*)d_in[10];
    const float* Wp_w = (const float*)d_in[11];
    const float* Wp_b = (const float*)d_in[12];

    cudaFuncSetAttribute(attn_mma_kernel,
                         cudaFuncAttributeMaxDynamicSharedMemorySize, ATT_SMEM);
    cudaFuncSetAttribute(gemm_qkv_bf16,
                         cudaFuncAttributeMaxDynamicSharedMemorySize, QKV_SMEM);
    cudaFuncSetAttribute(gemm_out_bf16,
                         cudaFuncAttributeMaxDynamicSharedMemorySize, OUT_SMEM);

    gemm_qkv_bf16<<<dim3(H_/128, (B_*L_)/128, 3), 512, QKV_SMEM>>>(
        q_in, k_in, v_in, Wq_w, Wq_b, Wk_w, Wk_b, Wv_w, Wv_b);

    wp_convert_kernel<<<(4096*D_)/256, 256>>>(Wp_w);

    attn_mma_kernel<<<dim3(L_/128, B_*NH), 512, ATT_SMEM>>>(Wp_b);

    gemm_out_bf16<<<dim3(H_/128, (B_*L_)/128), 512, OUT_SMEM>>>(Wo_w, Wo_b, (float*)d_out);
}

// round 8
// speedup vs baseline: 1.3407x; 1.3407x over previous
#include <cuda_runtime.h>
#include <cuda_bf16.h>
#include <cstdint>

#define B_  4
#define L_  2048
#define H_  512
#define NH  8
#define D_  64

// ---------------- scratch (static device globals; no allocation) ----------------
__device__ __nv_bfloat16 g_Qbf[B_*NH*L_*D_];   // (b,h,l,d), scaled by 0.125*log2e
__device__ __nv_bfloat16 g_Kbf[B_*NH*L_*D_];
__device__ __nv_bfloat16 g_Wpbf[4096*D_];      // rows >= 4095 zero-padded
__device__ float g_V[B_*NH*L_*D_];             // fp32 head layout
__device__ float g_Diag[B_*NH*L_];             // softmax diagonal values

__device__ __forceinline__ float fast_exp2(float x) {
    float y; asm("ex2.approx.f32 %0, %1;" : "=f"(y) : "f"(x)); return y;
}
__device__ __forceinline__ void mma16816(float* c, const uint32_t* a,
                                         uint32_t b0, uint32_t b1) {
    asm volatile(
        "mma.sync.aligned.m16n8k16.row.col.f32.bf16.bf16.f32 "
        "{%0,%1,%2,%3}, {%4,%5,%6,%7}, {%8,%9}, {%0,%1,%2,%3};"
        : "+f"(c[0]), "+f"(c[1]), "+f"(c[2]), "+f"(c[3])
        : "r"(a[0]), "r"(a[1]), "r"(a[2]), "r"(a[3]), "r"(b0), "r"(b1));
}
__device__ __forceinline__ void ldsm_x4(uint32_t* r, uint32_t addr) {
    asm volatile("ldmatrix.sync.aligned.m8n8.x4.shared.b16 {%0,%1,%2,%3}, [%4];"
        : "=r"(r[0]), "=r"(r[1]), "=r"(r[2]), "=r"(r[3]) : "r"(addr));
}
__device__ __forceinline__ uint32_t smem_u32(const void* p) {
    uint32_t a;
    asm("{ .reg .u64 t; cvta.to.shared.u64 t, %1; cvt.u32.u64 %0, t; }" : "=r"(a) : "l"(p));
    return a;
}
__device__ __forceinline__ void cp16(uint32_t s, const void* g) {
    asm volatile("cp.async.cg.shared.global [%0], [%1], 16;" :: "r"(s), "l"(g));
}
#define CP_COMMIT() asm volatile("cp.async.commit_group;" ::: "memory")

// A-operand ldmatrix base address: rows rb.., pitch-72 bf16 tile
__device__ __forceinline__ uint32_t ldsm_a_addr(const __nv_bfloat16* base, int rb, int lane) {
    return smem_u32(base + (rb + (lane & 15))*72 + ((lane >> 4) & 1)*8);
}
// B-operand ldmatrix base (covers 2 adjacent nf): rows nb..nb+15
__device__ __forceinline__ uint32_t ldsm_b_addr(const __nv_bfloat16* base, int nb, int lane) {
    return smem_u32(base + (nb + ((lane >> 4) & 1)*8 + (lane & 7))*72 + ((lane >> 3) & 1)*8);
}

// ---------------- Kernel 1: QKV projections, bf16 HMMA (round-6 + ldmatrix) -----
__global__ __launch_bounds__(256, 2)
void gemm_qkv_bf16(const float* __restrict__ q_in, const float* __restrict__ k_in,
                   const float* __restrict__ v_in,
                   const float* __restrict__ Wq, const float* __restrict__ bq,
                   const float* __restrict__ Wk, const float* __restrict__ bk,
                   const float* __restrict__ Wv, const float* __restrict__ bv)
{
    __shared__ __nv_bfloat16 Ab[128*72];
    __shared__ __nv_bfloat16 Wb[128*72];

    int mode = blockIdx.z;
    const float *A, *W, *bias;
    if (mode == 0)      { A = q_in; W = Wq; bias = bq; }
    else if (mode == 1) { A = k_in; W = Wk; bias = bk; }
    else                { A = v_in; W = Wv; bias = bv; }

    int m0 = blockIdx.y * 128, n0 = blockIdx.x * 128;
    int tid = threadIdx.x, lane = tid & 31, w = tid >> 5;
    int wr = w >> 1, wc = w & 1, g = lane >> 2, qd = lane & 3;
    int rl = tid >> 4, c4 = (tid & 15) * 4;

    const uint32_t qa0 = ldsm_a_addr(Ab, wr*32, lane);
    const uint32_t qa1 = qa0 + 16*72*2;
    const uint32_t wba = ldsm_b_addr(Wb, wc*64, lane);

    float acc[2][8][4] = {};

    for (int k0 = 0; k0 < H_; k0 += 64) {
        __syncthreads();
        #pragma unroll
        for (int i = 0; i < 8; i++) {
            int r = i*16 + rl;
            float4 va = *(const float4*)&A[(size_t)(m0 + r) * H_ + k0 + c4];
            float4 wv = *(const float4*)&W[(size_t)(n0 + r) * H_ + k0 + c4];
            __nv_bfloat162* pa = (__nv_bfloat162*)(Ab + r*72 + c4);
            pa[0] = __halves2bfloat162(__float2bfloat16(va.x), __float2bfloat16(va.y));
            pa[1] = __halves2bfloat162(__float2bfloat16(va.z), __float2bfloat16(va.w));
            __nv_bfloat162* pw = (__nv_bfloat162*)(Wb + r*72 + c4);
            pw[0] = __halves2bfloat162(__float2bfloat16(wv.x), __float2bfloat16(wv.y));
            pw[1] = __halves2bfloat162(__float2bfloat16(wv.z), __float2bfloat16(wv.w));
        }
        __syncthreads();
        #pragma unroll
        for (int kk = 0; kk < 4; kk++) {
            uint32_t a0[4], a1[4];
            ldsm_x4(a0, qa0 + kk*32);
            ldsm_x4(a1, qa1 + kk*32);
            #pragma unroll
            for (int p = 0; p < 4; p++) {
                uint32_t bb[4];
                ldsm_x4(bb, wba + p*(16*72*2) + kk*32);
                mma16816(acc[0][2*p+0], a0, bb[0], bb[1]);
                mma16816(acc[0][2*p+1], a0, bb[2], bb[3]);
                mma16816(acc[1][2*p+0], a1, bb[0], bb[1]);
                mma16816(acc[1][2*p+1], a1, bb[2], bb[3]);
            }
        }
    }

    const float qs = 0.125f * 1.4426950408889634f;
    #pragma unroll
    for (int mf = 0; mf < 2; mf++) {
        int rg = m0 + wr*32 + mf*16 + g;
        int b = rg >> 11, l = rg & (L_ - 1);
        #pragma unroll
        for (int nf = 0; nf < 8; nf++) {
            int n = n0 + wc*64 + nf*8 + qd*2;
            int h = n >> 6, d = n & 63;
            float b0 = bias[n], b1 = bias[n+1];
            float v00 = acc[mf][nf][0] + b0, v01 = acc[mf][nf][1] + b1;
            float v10 = acc[mf][nf][2] + b0, v11 = acc[mf][nf][3] + b1;
            size_t o0 = ((size_t)(b*NH + h) * L_ + l) * D_ + d;
            size_t o1 = o0 + 8*D_;
            if (mode == 0) {
                *(__nv_bfloat162*)(g_Qbf + o0) =
                    __halves2bfloat162(__float2bfloat16(v00*qs), __float2bfloat16(v01*qs));
                *(__nv_bfloat162*)(g_Qbf + o1) =
                    __halves2bfloat162(__float2bfloat16(v10*qs), __float2bfloat16(v11*qs));
            } else if (mode == 1) {
                *(__nv_bfloat162*)(g_Kbf + o0) =
                    __halves2bfloat162(__float2bfloat16(v00), __float2bfloat16(v01));
                *(__nv_bfloat162*)(g_Kbf + o1) =
                    __halves2bfloat162(__float2bfloat16(v10), __float2bfloat16(v11));
            } else {
                *(float2*)(g_V + o0) = make_float2(v00, v01);
                *(float2*)(g_V + o1) = make_float2(v10, v11);
            }
        }
    }
}

// ---------------- Kernel 1b: convert Wp to padded bf16 --------------------------
__global__ __launch_bounds__(256)
void wp_convert_kernel(const float* __restrict__ Wp)
{
    int idx = blockIdx.x * 256 + threadIdx.x;   // < 4096*64
    int r = idx >> 6;
    g_Wpbf[idx] = __float2bfloat16(r < 2*L_ - 1 ? Wp[idx] : 0.f);
}

// ---------------- Kernel 2: HMMA score pass, rolling-P ring, async + ldmatrix ---
#define PSP 520
#define AOFF_KS0 18432
#define AOFF_KS1 36864
#define AOFF_WS0 55296
#define AOFF_WS1 73728
#define AOFF_PS  92160
#define AOFF_WB  225280
#define AOFF_SD  226304
#define AOFF_RED 226816
#define ATT_SMEM 228864

__global__ __launch_bounds__(512, 1)
void attn_mma_kernel(const float* __restrict__ Wpb)
{
    extern __shared__ char smc[];
    __nv_bfloat16* Qs  = (__nv_bfloat16*)(smc);
    __nv_bfloat16* Psm = (__nv_bfloat16*)(smc + AOFF_PS);
    float* wbn   = (float*)(smc + AOFF_WB);    // [2][128]
    float* sdArr = (float*)(smc + AOFF_SD);
    float* red   = (float*)(smc + AOFF_RED);   // [4][128]

    const int tid = threadIdx.x;
    const int lane = tid & 31, w = tid >> 5;
    const int wr = w >> 2, wc = w & 3;
    const int g = lane >> 2, qd = lane & 3;
    const int bh = blockIdx.y, it = blockIdx.x;
    const int i0 = it * 128;
    const int rbase0 = 1920 - 128*it;

    const uint32_t ks_s[2] = { smem_u32(smc + AOFF_KS0), smem_u32(smc + AOFF_KS1) };
    const uint32_t ws_s[2] = { smem_u32(smc + AOFF_WS0), smem_u32(smc + AOFF_WS1) };

    auto cp_tile = [&](uint32_t sbase, const __nv_bfloat16* gsrc) {
        const uint4* g4 = (const uint4*)gsrc;
        #pragma unroll
        for (int t = tid; t < 1024; t += 512) {
            int r = t >> 3, c = t & 7;
            cp16(sbase + (r*72 + c*8)*2, g4 + t);
        }
    };

    {
        const uint4* Qg4 = (const uint4*)(g_Qbf + ((size_t)bh * L_ + i0) * D_);
        for (int t = tid; t < 1024; t += 512) {
            int r = t >> 3, c = t & 7;
            *(uint4*)(Qs + r*72 + c*8) = Qg4[t];
        }
    }
    cp_tile(ks_s[0], g_Kbf + (size_t)bh * L_ * D_);
    cp_tile(ws_s[1], g_Wpbf + (size_t)rbase0 * D_);
    cp_tile(ws_s[0], g_Wpbf + (size_t)(rbase0 + 128) * D_);
    CP_COMMIT();
    if (tid < 128) {
        wbn[128 + tid] = Wpb[rbase0 + tid] * 1.4426950408889634f;
        wbn[tid]       = Wpb[rbase0 + 128 + tid] * 1.4426950408889634f;
    }
    asm volatile("cp.async.wait_group 0;" ::: "memory");
    __syncthreads();

    // ldmatrix bases (Q fixed; K/W depend on buffer, offset computed per use)
    const uint32_t qa0 = ldsm_a_addr(Qs, wr*32, lane);
    const uint32_t qa1 = qa0 + 16*72*2;
    const uint32_t boff = ((((lane >> 4) & 1)*8 + (lane & 7))*72 + ((lane >> 3) & 1)*8)*2;
    const uint32_t bline = wc*32*72*2;

    auto pblock = [&](uint32_t ws_base, const float* wb, int slot) {
        float accP[2][4][4] = {};
        const uint32_t wb0a = ws_base + bline + boff;
        const uint32_t wb1a = wb0a + 16*72*2;
        #pragma unroll
        for (int kk = 0; kk < 4; kk++) {
            uint32_t a0[4], a1[4], b0v[4], b1v[4];
            ldsm_x4(a0, qa0 + kk*32);
            ldsm_x4(a1, qa1 + kk*32);
            ldsm_x4(b0v, wb0a + kk*32);
            ldsm_x4(b1v, wb1a + kk*32);
            mma16816(accP[0][0], a0, b0v[0], b0v[1]);
            mma16816(accP[0][1], a0, b0v[2], b0v[3]);
            mma16816(accP[0][2], a0, b1v[0], b1v[1]);
            mma16816(accP[0][3], a0, b1v[2], b1v[3]);
            mma16816(accP[1][0], a1, b0v[0], b0v[1]);
            mma16816(accP[1][1], a1, b0v[2], b0v[3]);
            mma16816(accP[1][2], a1, b1v[0], b1v[1]);
            mma16816(accP[1][3], a1, b1v[2], b1v[3]);
        }
        int pb = slot * 128;
        #pragma unroll
        for (int mf = 0; mf < 2; mf++) {
            int r0 = wr*32 + mf*16 + g, r1 = r0 + 8;
            #pragma unroll
            for (int nf = 0; nf < 4; nf++) {
                int c = wc*32 + nf*8 + qd*2;
                float b0 = wb[c], b1 = wb[c+1];
                __nv_bfloat16 v00 = __float2bfloat16(accP[mf][nf][0] + b0);
                __nv_bfloat16 v01 = __float2bfloat16(accP[mf][nf][1] + b1);
                __nv_bfloat16 v10 = __float2bfloat16(accP[mf][nf][2] + b0);
                __nv_bfloat16 v11 = __float2bfloat16(accP[mf][nf][3] + b1);
                Psm[r0*PSP + pb + c]     = v00;
                Psm[r0*PSP + pb + c + 1] = v01;
                Psm[r1*PSP + pb + c]     = v10;
                Psm[r1*PSP + pb + c + 1] = v11;
                if (slot == 0) {
                    Psm[r0*PSP + 384 + c]     = v00;
                    Psm[r0*PSP + 384 + c + 1] = v01;
                    Psm[r1*PSP + 384 + c]     = v10;
                    Psm[r1*PSP + 384 + c + 1] = v11;
                }
            }
        }
    };

    int sigma = (rbase0 >> 7) % 3;
    pblock(ws_s[1], wbn + 128, sigma);

    float rs[4] = {0.f, 0.f, 0.f, 0.f};

    for (int jt = 0; jt < L_/128; jt++) {
        int cur = jt & 1, nxt = cur ^ 1;
        int s_w = sigma + 1; if (s_w == 3) s_w = 0;
        __syncthreads();

        if (jt < 15) {
            cp_tile(ks_s[nxt], g_Kbf + ((size_t)bh * L_ + (jt+1)*128) * D_);
            cp_tile(ws_s[nxt], g_Wpbf + (size_t)(rbase0 + (jt+2)*128) * D_);
            CP_COMMIT();
            if (tid < 128) {
                int idx = rbase0 + (jt+2)*128 + tid;
                wbn[nxt*128 + tid] = (idx < 2*L_ - 1)
                                   ? Wpb[idx] * 1.4426950408889634f : 0.f;
            }
            asm volatile("cp.async.wait_group 1;" ::: "memory");
        } else {
            asm volatile("cp.async.wait_group 0;" ::: "memory");
        }
        __syncthreads();

        pblock(ws_s[cur], wbn + cur*128, s_w);

        float accS[2][4][4] = {};
        {
            const uint32_t kb0a = ks_s[cur] + bline + boff;
            const uint32_t kb1a = kb0a + 16*72*2;
            #pragma unroll
            for (int kk = 0; kk < 4; kk++) {
                uint32_t a0[4], a1[4], b0v[4], b1v[4];
                ldsm_x4(a0, qa0 + kk*32);
                ldsm_x4(a1, qa1 + kk*32);
                ldsm_x4(b0v, kb0a + kk*32);
                ldsm_x4(b1v, kb1a + kk*32);
                mma16816(accS[0][0], a0, b0v[0], b0v[1]);
                mma16816(accS[0][1], a0, b0v[2], b0v[3]);
                mma16816(accS[0][2], a0, b1v[0], b1v[1]);
                mma16816(accS[0][3], a0, b1v[2], b1v[3]);
                mma16816(accS[1][0], a1, b0v[0], b0v[1]);
                mma16816(accS[1][1], a1, b0v[2], b0v[3]);
                mma16816(accS[1][2], a1, b1v[0], b1v[1]);
                mma16816(accS[1][3], a1, b1v[2], b1v[3]);
            }
        }
        __syncthreads();

        bool dt = (jt == it);
        int off = sigma*128 + 127;
        #pragma unroll
        for (int mf = 0; mf < 2; mf++) {
            int r0 = wr*32 + mf*16 + g, r1 = r0 + 8;
            const __nv_bfloat16* base0 = Psm + r0*PSP + off - r0;
            const __nv_bfloat16* base1 = Psm + r1*PSP + off - r1;
            #pragma unroll
            for (int nf = 0; nf < 4; nf++) {
                int j = wc*32 + nf*8 + qd*2;
                float t00 = accS[mf][nf][0] + __bfloat162float(base0[j]);
                float t01 = accS[mf][nf][1] + __bfloat162float(base0[j+1]);
                float t10 = accS[mf][nf][2] + __bfloat162float(base1[j]);
                float t11 = accS[mf][nf][3] + __bfloat162float(base1[j+1]);
                rs[mf*2+0] += fast_exp2(t00) + fast_exp2(t01);
                rs[mf*2+1] += fast_exp2(t10) + fast_exp2(t11);
                if (dt) {
                    if (j == r0)          sdArr[r0] = t00;
                    else if (j + 1 == r0) sdArr[r0] = t01;
                    if (j == r1)          sdArr[r1] = t10;
                    else if (j + 1 == r1) sdArr[r1] = t11;
                }
            }
        }
        sigma = s_w;
    }

    #pragma unroll
    for (int k = 0; k < 4; k++) {
        rs[k] += __shfl_xor_sync(0xffffffffu, rs[k], 1);
        rs[k] += __shfl_xor_sync(0xffffffffu, rs[k], 2);
    }
    if (qd == 0) {
        int base = wc*128 + wr*32 + g;
        red[base]      = rs[0];
        red[base + 8]  = rs[1];
        red[base + 16] = rs[2];
        red[base + 24] = rs[3];
    }
    __syncthreads();
    if (tid < 128) {
        float r = red[tid] + red[128 + tid] + red[256 + tid] + red[384 + tid];
        g_Diag[(size_t)bh * L_ + i0 + tid] = fast_exp2(sdArr[tid]) / r;
    }
}

// ---------------- Kernel 3: O projection (round-6 + ldmatrix), fused diag*V -----
__global__ __launch_bounds__(256, 2)
void gemm_out_bf16(const float* __restrict__ Wo, const float* __restrict__ bo,
                   float* __restrict__ out)
{
    __shared__ __nv_bfloat16 Ab[128*72];
    __shared__ __nv_bfloat16 Wb[128*72];

    int m0 = blockIdx.y * 128, n0 = blockIdx.x * 128;
    int tid = threadIdx.x, lane = tid & 31, w = tid >> 5;
    int wr = w >> 1, wc = w & 1, g = lane >> 2, qd = lane & 3;
    int rl = tid >> 4, c4 = (tid & 15) * 4;

    const uint32_t qa0 = ldsm_a_addr(Ab, wr*32, lane);
    const uint32_t qa1 = qa0 + 16*72*2;
    const uint32_t wba = ldsm_b_addr(Wb, wc*64, lane);

    float acc[2][8][4] = {};

    for (int k0 = 0; k0 < H_; k0 += 64) {
        int h = k0 >> 6;
        __syncthreads();
        #pragma unroll
        for (int i = 0; i < 8; i++) {
            int r = i*16 + rl;
            int rg = m0 + r;
            int b = rg >> 11, l = rg & (L_ - 1);
            size_t vrow = (size_t)(b*NH + h) * L_ + l;
            float dg = g_Diag[vrow];
            float4 va = *(const float4*)&g_V[vrow * D_ + c4];
            float4 wv = *(const float4*)&Wo[(size_t)(n0 + r) * H_ + k0 + c4];
            __nv_bfloat162* pa = (__nv_bfloat162*)(Ab + r*72 + c4);
            pa[0] = __halves2bfloat162(__float2bfloat16(va.x*dg), __float2bfloat16(va.y*dg));
            pa[1] = __halves2bfloat162(__float2bfloat16(va.z*dg), __float2bfloat16(va.w*dg));
            __nv_bfloat162* pw = (__nv_bfloat162*)(Wb + r*72 + c4);
            pw[0] = __halves2bfloat162(__float2bfloat16(wv.x), __float2bfloat16(wv.y));
            pw[1] = __halves2bfloat162(__float2bfloat16(wv.z), __float2bfloat16(wv.w));
        }
        __syncthreads();
        #pragma unroll
        for (int kk = 0; kk < 4; kk++) {
            uint32_t a0[4], a1[4];
            ldsm_x4(a0, qa0 + kk*32);
            ldsm_x4(a1, qa1 + kk*32);
            #pragma unroll
            for (int p = 0; p < 4; p++) {
                uint32_t bb[4];
                ldsm_x4(bb, wba + p*(16*72*2) + kk*32);
                mma16816(acc[0][2*p+0], a0, bb[0], bb[1]);
                mma16816(acc[0][2*p+1], a0, bb[2], bb[3]);
                mma16816(acc[1][2*p+0], a1, bb[0], bb[1]);
                mma16816(acc[1][2*p+1], a1, bb[2], bb[3]);
            }
        }
    }

    #pragma unroll
    for (int mf = 0; mf < 2; mf++) {
        int rg = m0 + wr*32 + mf*16 + g;
        #pragma unroll
        for (int nf = 0; nf < 8; nf++) {
            int n = n0 + wc*64 + nf*8 + qd*2;
            float b0 = bo[n], b1 = bo[n+1];
            *(float2*)(out + (size_t)rg * H_ + n) =
                make_float2(acc[mf][nf][0] + b0, acc[mf][nf][1] + b1);
            *(float2*)(out + (size_t)(rg + 8) * H_ + n) =
                make_float2(acc[mf][nf][2] + b0, acc[mf][nf][3] + b1);
        }
    }
}

// ---------------- launch --------------------------------------------------------
extern "C" void kernel_launch(void* const* d_in, const int* in_sizes, int n_in,
                              void* d_out, int out_size)
{
    const float* q_in = (const float*)d_in[0];
    const float* k_in = (const float*)d_in[1];
    const float* v_in = (const float*)d_in[2];
    const float* Wq_w = (const float*)d_in[3];
    const float* Wq_b = (const float*)d_in[4];
    const float* Wk_w = (const float*)d_in[5];
    const float* Wk_b = (const float*)d_in[6];
    const float* Wv_w = (const float*)d_in[7];
    const float* Wv_b = (const float*)d_in[8];
    const float* Wo_w = (const float*)d_in[9];
    const float* Wo_b = (const float*)d_in[10];
    const float* Wp_w = (const float*)d_in[11];
    const float* Wp_b = (const float*)d_in[12];

    cudaFuncSetAttribute(attn_mma_kernel,
                         cudaFuncAttributeMaxDynamicSharedMemorySize, ATT_SMEM);

    gemm_qkv_bf16<<<dim3(H_/128, (B_*L_)/128, 3), 256>>>(
        q_in, k_in, v_in, Wq_w, Wq_b, Wk_w, Wk_b, Wv_w, Wv_b);

    wp_convert_kernel<<<(4096*D_)/256, 256>>>(Wp_w);

    attn_mma_kernel<<<dim3(L_/128, B_*NH), 512, ATT_SMEM>>>(Wp_b);

    gemm_out_bf16<<<dim3(H_/128, (B_*L_)/128), 256>>>(Wo_w, Wo_b, (float*)d_out);
}

// round 9
// speedup vs baseline: 1.4404x; 1.0743x over previous
#include <cuda_runtime.h>
#include <cuda_bf16.h>
#include <cstdint>

#define B_  4
#define L_  2048
#define H_  512
#define NH  8
#define D_  64
#define KP  40     // bf16 pitch for 32-wide K-chunk tiles

// ---------------- scratch (static device globals; no allocation) ----------------
__device__ __nv_bfloat16 g_Qbf[B_*NH*L_*D_];   // (b,h,l,d), scaled by 0.125*log2e
__device__ __nv_bfloat16 g_Kbf[B_*NH*L_*D_];
__device__ __nv_bfloat16 g_Wpbf[4096*D_];      // rows >= 4095 zero-padded
__device__ float g_V[B_*NH*L_*D_];             // fp32 head layout
__device__ float g_Diag[B_*NH*L_];             // softmax diagonal values

__device__ __forceinline__ float fast_exp2(float x) {
    float y; asm("ex2.approx.f32 %0, %1;" : "=f"(y) : "f"(x)); return y;
}
__device__ __forceinline__ void mma16816(float* c, const uint32_t* a,
                                         uint32_t b0, uint32_t b1) {
    asm volatile(
        "mma.sync.aligned.m16n8k16.row.col.f32.bf16.bf16.f32 "
        "{%0,%1,%2,%3}, {%4,%5,%6,%7}, {%8,%9}, {%0,%1,%2,%3};"
        : "+f"(c[0]), "+f"(c[1]), "+f"(c[2]), "+f"(c[3])
        : "r"(a[0]), "r"(a[1]), "r"(a[2]), "r"(a[3]), "r"(b0), "r"(b1));
}
__device__ __forceinline__ void ldsm_x4(uint32_t* r, uint32_t addr) {
    asm volatile("ldmatrix.sync.aligned.m8n8.x4.shared.b16 {%0,%1,%2,%3}, [%4];"
        : "=r"(r[0]), "=r"(r[1]), "=r"(r[2]), "=r"(r[3]) : "r"(addr));
}
__device__ __forceinline__ uint32_t smem_u32(const void* p) {
    uint32_t a;
    asm("{ .reg .u64 t; cvta.to.shared.u64 t, %1; cvt.u32.u64 %0, t; }" : "=r"(a) : "l"(p));
    return a;
}
__device__ __forceinline__ void cp16(uint32_t s, const void* g) {
    asm volatile("cp.async.cg.shared.global [%0], [%1], 16;" :: "r"(s), "l"(g));
}
#define CP_COMMIT() asm volatile("cp.async.commit_group;" ::: "memory")

__device__ __forceinline__ __nv_bfloat162 cvt2(float x, float y) {
    return __halves2bfloat162(__float2bfloat16(x), __float2bfloat16(y));
}
// pitch-72 ldmatrix helpers (attention kernel)
__device__ __forceinline__ uint32_t ldsm_a_addr(const __nv_bfloat16* base, int rb, int lane) {
    return smem_u32(base + (rb + (lane & 15))*72 + ((lane >> 4) & 1)*8);
}

// ---------------- Kernel 1: QKV projections, reg-prefetch pipelined HMMA --------
__global__ __launch_bounds__(256, 2)
void gemm_qkv_bf16(const float* __restrict__ q_in, const float* __restrict__ k_in,
                   const float* __restrict__ v_in,
                   const float* __restrict__ Wq, const float* __restrict__ bq,
                   const float* __restrict__ Wk, const float* __restrict__ bk,
                   const float* __restrict__ Wv, const float* __restrict__ bv)
{
    __shared__ __nv_bfloat16 Ab[2][128*KP];
    __shared__ __nv_bfloat16 Wb[2][128*KP];

    int mode = blockIdx.z;
    const float *A, *W, *bias;
    if (mode == 0)      { A = q_in; W = Wq; bias = bq; }
    else if (mode == 1) { A = k_in; W = Wk; bias = bk; }
    else                { A = v_in; W = Wv; bias = bv; }

    const int m0 = blockIdx.y * 128, n0 = blockIdx.x * 128;
    const int tid = threadIdx.x, lane = tid & 31, w = tid >> 5;
    const int wr = w >> 1, wc = w & 1, g = lane >> 2, qd = lane & 3;
    const int rr = tid >> 3;            // 0..31
    const int c4 = (tid & 7) * 4;       // 0..28

    float4 ra[4], rw[4];
    auto ldg_chunk = [&](int kc) {
        const float* Ag = A + (size_t)m0 * H_ + kc*32;
        const float* Wg = W + (size_t)n0 * H_ + kc*32;
        #pragma unroll
        for (int i = 0; i < 4; i++) {
            int r = i*32 + rr;
            ra[i] = *(const float4*)&Ag[(size_t)r * H_ + c4];
            rw[i] = *(const float4*)&Wg[(size_t)r * H_ + c4];
        }
    };
    auto sts_chunk = [&](int buf) {
        #pragma unroll
        for (int i = 0; i < 4; i++) {
            int r = i*32 + rr;
            __nv_bfloat162* pa = (__nv_bfloat162*)(Ab[buf] + r*KP + c4);
            pa[0] = cvt2(ra[i].x, ra[i].y);
            pa[1] = cvt2(ra[i].z, ra[i].w);
            __nv_bfloat162* pw = (__nv_bfloat162*)(Wb[buf] + r*KP + c4);
            pw[0] = cvt2(rw[i].x, rw[i].y);
            pw[1] = cvt2(rw[i].z, rw[i].w);
        }
    };

    uint32_t qaA[2], wbaA[2];
    #pragma unroll
    for (int b = 0; b < 2; b++) {
        qaA[b]  = smem_u32(Ab[b] + (wr*32 + (lane & 15))*KP + ((lane >> 4) & 1)*8);
        wbaA[b] = smem_u32(Wb[b] + (wc*64 + ((lane >> 4) & 1)*8 + (lane & 7))*KP
                           + ((lane >> 3) & 1)*8);
    }

    float acc[2][8][4] = {};

    ldg_chunk(0);
    sts_chunk(0);
    ldg_chunk(1);

    for (int kc = 0; kc < 16; kc++) {
        int cur = kc & 1;
        __syncthreads();
        #pragma unroll
        for (int kk = 0; kk < 2; kk++) {
            uint32_t a0[4], a1[4];
            ldsm_x4(a0, qaA[cur] + kk*32);
            ldsm_x4(a1, qaA[cur] + 16*KP*2 + kk*32);
            #pragma unroll
            for (int p = 0; p < 4; p++) {
                uint32_t bb[4];
                ldsm_x4(bb, wbaA[cur] + p*(16*KP*2) + kk*32);
                mma16816(acc[0][2*p+0], a0, bb[0], bb[1]);
                mma16816(acc[0][2*p+1], a0, bb[2], bb[3]);
                mma16816(acc[1][2*p+0], a1, bb[0], bb[1]);
                mma16816(acc[1][2*p+1], a1, bb[2], bb[3]);
            }
        }
        if (kc < 15) {
            sts_chunk(cur ^ 1);
            if (kc < 14) ldg_chunk(kc + 2);
        }
    }

    const float qs = 0.125f * 1.4426950408889634f;
    #pragma unroll
    for (int mf = 0; mf < 2; mf++) {
        int rg = m0 + wr*32 + mf*16 + g;
        int b = rg >> 11, l = rg & (L_ - 1);
        #pragma unroll
        for (int nf = 0; nf < 8; nf++) {
            int n = n0 + wc*64 + nf*8 + qd*2;
            int h = n >> 6, d = n & 63;
            float b0 = bias[n], b1 = bias[n+1];
            float v00 = acc[mf][nf][0] + b0, v01 = acc[mf][nf][1] + b1;
            float v10 = acc[mf][nf][2] + b0, v11 = acc[mf][nf][3] + b1;
            size_t o0 = ((size_t)(b*NH + h) * L_ + l) * D_ + d;
            size_t o1 = o0 + 8*D_;
            if (mode == 0) {
                *(__nv_bfloat162*)(g_Qbf + o0) = cvt2(v00*qs, v01*qs);
                *(__nv_bfloat162*)(g_Qbf + o1) = cvt2(v10*qs, v11*qs);
            } else if (mode == 1) {
                *(__nv_bfloat162*)(g_Kbf + o0) = cvt2(v00, v01);
                *(__nv_bfloat162*)(g_Kbf + o1) = cvt2(v10, v11);
            } else {
                *(float2*)(g_V + o0) = make_float2(v00, v01);
                *(float2*)(g_V + o1) = make_float2(v10, v11);
            }
        }
    }
}

// ---------------- Kernel 1b: convert Wp to padded bf16 --------------------------
__global__ __launch_bounds__(256)
void wp_convert_kernel(const float* __restrict__ Wp)
{
    int idx = blockIdx.x * 256 + threadIdx.x;   // < 4096*64
    int r = idx >> 6;
    g_Wpbf[idx] = __float2bfloat16(r < 2*L_ - 1 ? Wp[idx] : 0.f);
}

// ---------------- Kernel 2: HMMA score pass (unchanged from round 8) ------------
#define PSP 520
#define AOFF_KS0 18432
#define AOFF_KS1 36864
#define AOFF_WS0 55296
#define AOFF_WS1 73728
#define AOFF_PS  92160
#define AOFF_WB  225280
#define AOFF_SD  226304
#define AOFF_RED 226816
#define ATT_SMEM 228864

__global__ __launch_bounds__(512, 1)
void attn_mma_kernel(const float* __restrict__ Wpb)
{
    extern __shared__ char smc[];
    __nv_bfloat16* Qs  = (__nv_bfloat16*)(smc);
    __nv_bfloat16* Psm = (__nv_bfloat16*)(smc + AOFF_PS);
    float* wbn   = (float*)(smc + AOFF_WB);    // [2][128]
    float* sdArr = (float*)(smc + AOFF_SD);
    float* red   = (float*)(smc + AOFF_RED);   // [4][128]

    const int tid = threadIdx.x;
    const int lane = tid & 31, w = tid >> 5;
    const int wr = w >> 2, wc = w & 3;
    const int g = lane >> 2, qd = lane & 3;
    const int bh = blockIdx.y, it = blockIdx.x;
    const int i0 = it * 128;
    const int rbase0 = 1920 - 128*it;

    const uint32_t ks_s[2] = { smem_u32(smc + AOFF_KS0), smem_u32(smc + AOFF_KS1) };
    const uint32_t ws_s[2] = { smem_u32(smc + AOFF_WS0), smem_u32(smc + AOFF_WS1) };

    auto cp_tile = [&](uint32_t sbase, const __nv_bfloat16* gsrc) {
        const uint4* g4 = (const uint4*)gsrc;
        #pragma unroll
        for (int t = tid; t < 1024; t += 512) {
            int r = t >> 3, c = t & 7;
            cp16(sbase + (r*72 + c*8)*2, g4 + t);
        }
    };

    {
        const uint4* Qg4 = (const uint4*)(g_Qbf + ((size_t)bh * L_ + i0) * D_);
        for (int t = tid; t < 1024; t += 512) {
            int r = t >> 3, c = t & 7;
            *(uint4*)(Qs + r*72 + c*8) = Qg4[t];
        }
    }
    cp_tile(ks_s[0], g_Kbf + (size_t)bh * L_ * D_);
    cp_tile(ws_s[1], g_Wpbf + (size_t)rbase0 * D_);
    cp_tile(ws_s[0], g_Wpbf + (size_t)(rbase0 + 128) * D_);
    CP_COMMIT();
    if (tid < 128) {
        wbn[128 + tid] = Wpb[rbase0 + tid] * 1.4426950408889634f;
        wbn[tid]       = Wpb[rbase0 + 128 + tid] * 1.4426950408889634f;
    }
    asm volatile("cp.async.wait_group 0;" ::: "memory");
    __syncthreads();

    const uint32_t qa0 = ldsm_a_addr(Qs, wr*32, lane);
    const uint32_t qa1 = qa0 + 16*72*2;
    const uint32_t boff = ((((lane >> 4) & 1)*8 + (lane & 7))*72 + ((lane >> 3) & 1)*8)*2;
    const uint32_t bline = wc*32*72*2;

    auto pblock = [&](uint32_t ws_base, const float* wb, int slot) {
        float accP[2][4][4] = {};
        const uint32_t wb0a = ws_base + bline + boff;
        const uint32_t wb1a = wb0a + 16*72*2;
        #pragma unroll
        for (int kk = 0; kk < 4; kk++) {
            uint32_t a0[4], a1[4], b0v[4], b1v[4];
            ldsm_x4(a0, qa0 + kk*32);
            ldsm_x4(a1, qa1 + kk*32);
            ldsm_x4(b0v, wb0a + kk*32);
            ldsm_x4(b1v, wb1a + kk*32);
            mma16816(accP[0][0], a0, b0v[0], b0v[1]);
            mma16816(accP[0][1], a0, b0v[2], b0v[3]);
            mma16816(accP[0][2], a0, b1v[0], b1v[1]);
            mma16816(accP[0][3], a0, b1v[2], b1v[3]);
            mma16816(accP[1][0], a1, b0v[0], b0v[1]);
            mma16816(accP[1][1], a1, b0v[2], b0v[3]);
            mma16816(accP[1][2], a1, b1v[0], b1v[1]);
            mma16816(accP[1][3], a1, b1v[2], b1v[3]);
        }
        int pb = slot * 128;
        #pragma unroll
        for (int mf = 0; mf < 2; mf++) {
            int r0 = wr*32 + mf*16 + g, r1 = r0 + 8;
            #pragma unroll
            for (int nf = 0; nf < 4; nf++) {
                int c = wc*32 + nf*8 + qd*2;
                float b0 = wb[c], b1 = wb[c+1];
                __nv_bfloat16 v00 = __float2bfloat16(accP[mf][nf][0] + b0);
                __nv_bfloat16 v01 = __float2bfloat16(accP[mf][nf][1] + b1);
                __nv_bfloat16 v10 = __float2bfloat16(accP[mf][nf][2] + b0);
                __nv_bfloat16 v11 = __float2bfloat16(accP[mf][nf][3] + b1);
                Psm[r0*PSP + pb + c]     = v00;
                Psm[r0*PSP + pb + c + 1] = v01;
                Psm[r1*PSP + pb + c]     = v10;
                Psm[r1*PSP + pb + c + 1] = v11;
                if (slot == 0) {
                    Psm[r0*PSP + 384 + c]     = v00;
                    Psm[r0*PSP + 384 + c + 1] = v01;
                    Psm[r1*PSP + 384 + c]     = v10;
                    Psm[r1*PSP + 384 + c + 1] = v11;
                }
            }
        }
    };

    int sigma = (rbase0 >> 7) % 3;
    pblock(ws_s[1], wbn + 128, sigma);

    float rs[4] = {0.f, 0.f, 0.f, 0.f};

    for (int jt = 0; jt < L_/128; jt++) {
        int cur = jt & 1, nxt = cur ^ 1;
        int s_w = sigma + 1; if (s_w == 3) s_w = 0;
        __syncthreads();

        if (jt < 15) {
            cp_tile(ks_s[nxt], g_Kbf + ((size_t)bh * L_ + (jt+1)*128) * D_);
            cp_tile(ws_s[nxt], g_Wpbf + (size_t)(rbase0 + (jt+2)*128) * D_);
            CP_COMMIT();
            if (tid < 128) {
                int idx = rbase0 + (jt+2)*128 + tid;
                wbn[nxt*128 + tid] = (idx < 2*L_ - 1)
                                   ? Wpb[idx] * 1.4426950408889634f : 0.f;
            }
            asm volatile("cp.async.wait_group 1;" ::: "memory");
        } else {
            asm volatile("cp.async.wait_group 0;" ::: "memory");
        }
        __syncthreads();

        pblock(ws_s[cur], wbn + cur*128, s_w);

        float accS[2][4][4] = {};
        {
            const uint32_t kb0a = ks_s[cur] + bline + boff;
            const uint32_t kb1a = kb0a + 16*72*2;
            #pragma unroll
            for (int kk = 0; kk < 4; kk++) {
                uint32_t a0[4], a1[4], b0v[4], b1v[4];
                ldsm_x4(a0, qa0 + kk*32);
                ldsm_x4(a1, qa1 + kk*32);
                ldsm_x4(b0v, kb0a + kk*32);
                ldsm_x4(b1v, kb1a + kk*32);
                mma16816(accS[0][0], a0, b0v[0], b0v[1]);
                mma16816(accS[0][1], a0, b0v[2], b0v[3]);
                mma16816(accS[0][2], a0, b1v[0], b1v[1]);
                mma16816(accS[0][3], a0, b1v[2], b1v[3]);
                mma16816(accS[1][0], a1, b0v[0], b0v[1]);
                mma16816(accS[1][1], a1, b0v[2], b0v[3]);
                mma16816(accS[1][2], a1, b1v[0], b1v[1]);
                mma16816(accS[1][3], a1, b1v[2], b1v[3]);
            }
        }
        __syncthreads();

        bool dt = (jt == it);
        int off = sigma*128 + 127;
        #pragma unroll
        for (int mf = 0; mf < 2; mf++) {
            int r0 = wr*32 + mf*16 + g, r1 = r0 + 8;
            const __nv_bfloat16* base0 = Psm + r0*PSP + off - r0;
            const __nv_bfloat16* base1 = Psm + r1*PSP + off - r1;
            #pragma unroll
            for (int nf = 0; nf < 4; nf++) {
                int j = wc*32 + nf*8 + qd*2;
                float t00 = accS[mf][nf][0] + __bfloat162float(base0[j]);
                float t01 = accS[mf][nf][1] + __bfloat162float(base0[j+1]);
                float t10 = accS[mf][nf][2] + __bfloat162float(base1[j]);
                float t11 = accS[mf][nf][3] + __bfloat162float(base1[j+1]);
                rs[mf*2+0] += fast_exp2(t00) + fast_exp2(t01);
                rs[mf*2+1] += fast_exp2(t10) + fast_exp2(t11);
                if (dt) {
                    if (j == r0)          sdArr[r0] = t00;
                    else if (j + 1 == r0) sdArr[r0] = t01;
                    if (j == r1)          sdArr[r1] = t10;
                    else if (j + 1 == r1) sdArr[r1] = t11;
                }
            }
        }
        sigma = s_w;
    }

    #pragma unroll
    for (int k = 0; k < 4; k++) {
        rs[k] += __shfl_xor_sync(0xffffffffu, rs[k], 1);
        rs[k] += __shfl_xor_sync(0xffffffffu, rs[k], 2);
    }
    if (qd == 0) {
        int base = wc*128 + wr*32 + g;
        red[base]      = rs[0];
        red[base + 8]  = rs[1];
        red[base + 16] = rs[2];
        red[base + 24] = rs[3];
    }
    __syncthreads();
    if (tid < 128) {
        float r = red[tid] + red[128 + tid] + red[256 + tid] + red[384 + tid];
        g_Diag[(size_t)bh * L_ + i0 + tid] = fast_exp2(sdArr[tid]) / r;
    }
}

// ---------------- Kernel 3: O projection, reg-prefetch pipeline, fused diag*V ---
__global__ __launch_bounds__(256, 2)
void gemm_out_bf16(const float* __restrict__ Wo, const float* __restrict__ bo,
                   float* __restrict__ out)
{
    __shared__ __nv_bfloat16 Ab[2][128*KP];
    __shared__ __nv_bfloat16 Wb[2][128*KP];

    const int m0 = blockIdx.y * 128, n0 = blockIdx.x * 128;
    const int tid = threadIdx.x, lane = tid & 31, w = tid >> 5;
    const int wr = w >> 1, wc = w & 1, g = lane >> 2, qd = lane & 3;
    const int rr = tid >> 3;
    const int c4 = (tid & 7) * 4;

    const int bq = m0 >> 11, l0 = m0 & (L_ - 1);

    float4 ra[4], rw[4];
    float dgv[4];
    auto ldg_chunk = [&](int kc) {
        int h = kc >> 1;
        const float* Ag = g_V + ((size_t)(bq*NH + h) * L_ + l0) * D_ + (kc & 1)*32;
        const float* Wg = Wo + (size_t)n0 * H_ + kc*32;
        const float* Dg = g_Diag + (size_t)(bq*NH + h) * L_ + l0;
        #pragma unroll
        for (int i = 0; i < 4; i++) {
            int r = i*32 + rr;
            ra[i]  = *(const float4*)&Ag[(size_t)r * D_ + c4];
            rw[i]  = *(const float4*)&Wg[(size_t)r * H_ + c4];
            dgv[i] = Dg[r];
        }
    };
    auto sts_chunk = [&](int buf) {
        #pragma unroll
        for (int i = 0; i < 4; i++) {
            int r = i*32 + rr;
            float d = dgv[i];
            __nv_bfloat162* pa = (__nv_bfloat162*)(Ab[buf] + r*KP + c4);
            pa[0] = cvt2(ra[i].x*d, ra[i].y*d);
            pa[1] = cvt2(ra[i].z*d, ra[i].w*d);
            __nv_bfloat162* pw = (__nv_bfloat162*)(Wb[buf] + r*KP + c4);
            pw[0] = cvt2(rw[i].x, rw[i].y);
            pw[1] = cvt2(rw[i].z, rw[i].w);
        }
    };

    uint32_t qaA[2], wbaA[2];
    #pragma unroll
    for (int b = 0; b < 2; b++) {
        qaA[b]  = smem_u32(Ab[b] + (wr*32 + (lane & 15))*KP + ((lane >> 4) & 1)*8);
        wbaA[b] = smem_u32(Wb[b] + (wc*64 + ((lane >> 4) & 1)*8 + (lane & 7))*KP
                           + ((lane >> 3) & 1)*8);
    }

    float acc[2][8][4] = {};

    ldg_chunk(0);
    sts_chunk(0);
    ldg_chunk(1);

    for (int kc = 0; kc < 16; kc++) {
        int cur = kc & 1;
        __syncthreads();
        #pragma unroll
        for (int kk = 0; kk < 2; kk++) {
            uint32_t a0[4], a1[4];
            ldsm_x4(a0, qaA[cur] + kk*32);
            ldsm_x4(a1, qaA[cur] + 16*KP*2 + kk*32);
            #pragma unroll
            for (int p = 0; p < 4; p++) {
                uint32_t bb[4];
                ldsm_x4(bb, wbaA[cur] + p*(16*KP*2) + kk*32);
                mma16816(acc[0][2*p+0], a0, bb[0], bb[1]);
                mma16816(acc[0][2*p+1], a0, bb[2], bb[3]);
                mma16816(acc[1][2*p+0], a1, bb[0], bb[1]);
                mma16816(acc[1][2*p+1], a1, bb[2], bb[3]);
            }
        }
        if (kc < 15) {
            sts_chunk(cur ^ 1);
            if (kc < 14) ldg_chunk(kc + 2);
        }
    }

    #pragma unroll
    for (int mf = 0; mf < 2; mf++) {
        int rg = m0 + wr*32 + mf*16 + g;
        #pragma unroll
        for (int nf = 0; nf < 8; nf++) {
            int n = n0 + wc*64 + nf*8 + qd*2;
            float b0 = bo[n], b1 = bo[n+1];
            *(float2*)(out + (size_t)rg * H_ + n) =
                make_float2(acc[mf][nf][0] + b0, acc[mf][nf][1] + b1);
            *(float2*)(out + (size_t)(rg + 8) * H_ + n) =
                make_float2(acc[mf][nf][2] + b0, acc[mf][nf][3] + b1);
        }
    }
}

// ---------------- launch --------------------------------------------------------
extern "C" void kernel_launch(void* const* d_in, const int* in_sizes, int n_in,
                              void* d_out, int out_size)
{
    const float* q_in = (const float*)d_in[0];
    const float* k_in = (const float*)d_in[1];
    const float* v_in = (const float*)d_in[2];
    const float* Wq_w = (const float*)d_in[3];
    const float* Wq_b = (const float*)d_in[4];
    const float* Wk_w = (const float*)d_in[5];
    const float* Wk_b = (const float*)d_in[6];
    const float* Wv_w = (const float*)d_in[7];
    const float* Wv_b = (const float*)d_in[8];
    const float* Wo_w = (const float*)d_in[9];
    const float* Wo_b = (const float*)d_in[10];
    const float* Wp_w = (const float*)d_in[11];
    const float* Wp_b = (const float*)d_in[12];

    cudaFuncSetAttribute(attn_mma_kernel,
                         cudaFuncAttributeMaxDynamicSharedMemorySize, ATT_SMEM);

    gemm_qkv_bf16<<<dim3(H_/128, (B_*L_)/128, 3), 256>>>(
        q_in, k_in, v_in, Wq_w, Wq_b, Wk_w, Wk_b, Wv_w, Wv_b);

    wp_convert_kernel<<<(4096*D_)/256, 256>>>(Wp_w);

    attn_mma_kernel<<<dim3(L_/128, B_*NH), 512, ATT_SMEM>>>(Wp_b);

    gemm_out_bf16<<<dim3(H_/128, (B_*L_)/128), 256>>>(Wo_w, Wo_b, (float*)d_out);
}

// round 10
// speedup vs baseline: 1.6762x; 1.1637x over previous
#include <cuda_runtime.h>
#include <cuda_bf16.h>
#include <cstdint>

#define B_  4
#define L_  2048
#define H_  512
#define NH  8
#define D_  64
#define KP  40     // bf16 pitch for 32-wide K-chunk tiles
#define LOG2E 1.4426950408889634f

// ---------------- scratch (static device globals; no allocation) ----------------
__device__ __nv_bfloat16 g_Qbf[B_*NH*L_*D_];   // (b,h,l,d), scaled by 0.125*log2e
__device__ __nv_bfloat16 g_Kbf[B_*NH*L_*D_];
__device__ __nv_bfloat16 g_Wpbf[4096*D_];      // rows >= 4095 zero-padded
__device__ float g_V[B_*NH*L_*D_];             // fp32 head layout
__device__ float g_Diag[B_*NH*L_];             // softmax diagonal values

__device__ __forceinline__ float fast_exp2(float x) {
    float y; asm("ex2.approx.f32 %0, %1;" : "=f"(y) : "f"(x)); return y;
}
__device__ __forceinline__ void mma16816(float* c, const uint32_t* a,
                                         uint32_t b0, uint32_t b1) {
    asm volatile(
        "mma.sync.aligned.m16n8k16.row.col.f32.bf16.bf16.f32 "
        "{%0,%1,%2,%3}, {%4,%5,%6,%7}, {%8,%9}, {%0,%1,%2,%3};"
        : "+f"(c[0]), "+f"(c[1]), "+f"(c[2]), "+f"(c[3])
        : "r"(a[0]), "r"(a[1]), "r"(a[2]), "r"(a[3]), "r"(b0), "r"(b1));
}
__device__ __forceinline__ void ldsm_x4(uint32_t* r, uint32_t addr) {
    asm volatile("ldmatrix.sync.aligned.m8n8.x4.shared.b16 {%0,%1,%2,%3}, [%4];"
        : "=r"(r[0]), "=r"(r[1]), "=r"(r[2]), "=r"(r[3]) : "r"(addr));
}
__device__ __forceinline__ uint32_t smem_u32(const void* p) {
    uint32_t a;
    asm("{ .reg .u64 t; cvta.to.shared.u64 t, %1; cvt.u32.u64 %0, t; }" : "=r"(a) : "l"(p));
    return a;
}
__device__ __forceinline__ void cp16(uint32_t s, const void* g) {
    asm volatile("cp.async.cg.shared.global [%0], [%1], 16;" :: "r"(s), "l"(g));
}
#define CP_COMMIT() asm volatile("cp.async.commit_group;" ::: "memory")

__device__ __forceinline__ __nv_bfloat162 cvt2(float x, float y) {
    return __halves2bfloat162(__float2bfloat16(x), __float2bfloat16(y));
}
// pitch-72 ldmatrix helper (attention kernel)
__device__ __forceinline__ uint32_t ldsm_a_addr(const __nv_bfloat16* base, int rb, int lane) {
    return smem_u32(base + (rb + (lane & 15))*72 + ((lane >> 4) & 1)*8);
}

// ---------------- Kernel 1: QKV projections + Wp convert (z==3) -----------------
__global__ __launch_bounds__(256, 2)
void gemm_qkv_bf16(const float* __restrict__ q_in, const float* __restrict__ k_in,
                   const float* __restrict__ v_in,
                   const float* __restrict__ Wq, const float* __restrict__ bq,
                   const float* __restrict__ Wk, const float* __restrict__ bk,
                   const float* __restrict__ Wv, const float* __restrict__ bv,
                   const float* __restrict__ Wp)
{
    int mode = blockIdx.z;
    if (mode == 3) {   // Wp -> padded bf16 (256 blocks x 1024 elems)
        int base = (blockIdx.y * 4 + blockIdx.x) * 1024 + threadIdx.x * 4;
        int r = base >> 6;
        float4 v = make_float4(0.f, 0.f, 0.f, 0.f);
        if (r < 2*L_ - 1) v = *(const float4*)&Wp[base];
        *(__nv_bfloat162*)(g_Wpbf + base)     = cvt2(v.x, v.y);
        *(__nv_bfloat162*)(g_Wpbf + base + 2) = cvt2(v.z, v.w);
        return;
    }

    __shared__ __nv_bfloat16 Ab[2][128*KP];
    __shared__ __nv_bfloat16 Wb[2][128*KP];

    const float *A, *W, *bias;
    if (mode == 0)      { A = q_in; W = Wq; bias = bq; }
    else if (mode == 1) { A = k_in; W = Wk; bias = bk; }
    else                { A = v_in; W = Wv; bias = bv; }

    const int m0 = blockIdx.y * 128, n0 = blockIdx.x * 128;
    const int tid = threadIdx.x, lane = tid & 31, w = tid >> 5;
    const int wr = w >> 1, wc = w & 1, g = lane >> 2, qd = lane & 3;
    const int rr = tid >> 3;
    const int c4 = (tid & 7) * 4;

    float4 ra[4], rw[4];
    auto ldg_chunk = [&](int kc) {
        const float* Ag = A + (size_t)m0 * H_ + kc*32;
        const float* Wg = W + (size_t)n0 * H_ + kc*32;
        #pragma unroll
        for (int i = 0; i < 4; i++) {
            int r = i*32 + rr;
            ra[i] = *(const float4*)&Ag[(size_t)r * H_ + c4];
            rw[i] = *(const float4*)&Wg[(size_t)r * H_ + c4];
        }
    };
    auto sts_chunk = [&](int buf) {
        #pragma unroll
        for (int i = 0; i < 4; i++) {
            int r = i*32 + rr;
            __nv_bfloat162* pa = (__nv_bfloat162*)(Ab[buf] + r*KP + c4);
            pa[0] = cvt2(ra[i].x, ra[i].y);
            pa[1] = cvt2(ra[i].z, ra[i].w);
            __nv_bfloat162* pw = (__nv_bfloat162*)(Wb[buf] + r*KP + c4);
            pw[0] = cvt2(rw[i].x, rw[i].y);
            pw[1] = cvt2(rw[i].z, rw[i].w);
        }
    };

    uint32_t qaA[2], wbaA[2];
    #pragma unroll
    for (int b = 0; b < 2; b++) {
        qaA[b]  = smem_u32(Ab[b] + (wr*32 + (lane & 15))*KP + ((lane >> 4) & 1)*8);
        wbaA[b] = smem_u32(Wb[b] + (wc*64 + ((lane >> 4) & 1)*8 + (lane & 7))*KP
                           + ((lane >> 3) & 1)*8);
    }

    float acc[2][8][4] = {};

    ldg_chunk(0);
    sts_chunk(0);
    ldg_chunk(1);

    for (int kc = 0; kc < 16; kc++) {
        int cur = kc & 1;
        __syncthreads();
        #pragma unroll
        for (int kk = 0; kk < 2; kk++) {
            uint32_t a0[4], a1[4];
            ldsm_x4(a0, qaA[cur] + kk*32);
            ldsm_x4(a1, qaA[cur] + 16*KP*2 + kk*32);
            #pragma unroll
            for (int p = 0; p < 4; p++) {
                uint32_t bb[4];
                ldsm_x4(bb, wbaA[cur] + p*(16*KP*2) + kk*32);
                mma16816(acc[0][2*p+0], a0, bb[0], bb[1]);
                mma16816(acc[0][2*p+1], a0, bb[2], bb[3]);
                mma16816(acc[1][2*p+0], a1, bb[0], bb[1]);
                mma16816(acc[1][2*p+1], a1, bb[2], bb[3]);
            }
        }
        if (kc < 15) {
            sts_chunk(cur ^ 1);
            if (kc < 14) ldg_chunk(kc + 2);
        }
    }

    const float qs = 0.125f * LOG2E;
    #pragma unroll
    for (int mf = 0; mf < 2; mf++) {
        int rg = m0 + wr*32 + mf*16 + g;
        int b = rg >> 11, l = rg & (L_ - 1);
        #pragma unroll
        for (int nf = 0; nf < 8; nf++) {
            int n = n0 + wc*64 + nf*8 + qd*2;
            int h = n >> 6, d = n & 63;
            float b0 = bias[n], b1 = bias[n+1];
            float v00 = acc[mf][nf][0] + b0, v01 = acc[mf][nf][1] + b1;
            float v10 = acc[mf][nf][2] + b0, v11 = acc[mf][nf][3] + b1;
            size_t o0 = ((size_t)(b*NH + h) * L_ + l) * D_ + d;
            size_t o1 = o0 + 8*D_;
            if (mode == 0) {
                *(__nv_bfloat162*)(g_Qbf + o0) = cvt2(v00*qs, v01*qs);
                *(__nv_bfloat162*)(g_Qbf + o1) = cvt2(v10*qs, v11*qs);
            } else if (mode == 1) {
                *(__nv_bfloat162*)(g_Kbf + o0) = cvt2(v00, v01);
                *(__nv_bfloat162*)(g_Kbf + o1) = cvt2(v10, v11);
            } else {
                *(float2*)(g_V + o0) = make_float2(v00, v01);
                *(float2*)(g_V + o1) = make_float2(v10, v11);
            }
        }
    }
}

// ---------------- Kernel 2: HMMA score pass, single-barrier pipelined -----------
#define PSP 520
#define AOFF_KS0 18432
#define AOFF_KS1 36864
#define AOFF_WS0 55296
#define AOFF_WS1 73728
#define AOFF_PS  92160
#define AOFF_WB  225280
#define AOFF_SD  226304
#define AOFF_RED 226816
#define ATT_SMEM 228864

__global__ __launch_bounds__(512, 1)
void attn_mma_kernel(const float* __restrict__ Wpb)
{
    extern __shared__ char smc[];
    __nv_bfloat16* Qs  = (__nv_bfloat16*)(smc);
    __nv_bfloat16* Psm = (__nv_bfloat16*)(smc + AOFF_PS);
    float* wbn   = (float*)(smc + AOFF_WB);    // [2][128]
    float* sdArr = (float*)(smc + AOFF_SD);
    float* red   = (float*)(smc + AOFF_RED);   // [4][128]

    const int tid = threadIdx.x;
    const int lane = tid & 31, w = tid >> 5;
    const int wr = w >> 2, wc = w & 3;
    const int g = lane >> 2, qd = lane & 3;
    const int bh = blockIdx.y, it = blockIdx.x;
    const int i0 = it * 128;
    const int rbase0 = 1920 - 128*it;

    const uint32_t ks_s[2] = { smem_u32(smc + AOFF_KS0), smem_u32(smc + AOFF_KS1) };
    const uint32_t ws_s[2] = { smem_u32(smc + AOFF_WS0), smem_u32(smc + AOFF_WS1) };

    auto cp_tile = [&](uint32_t sbase, const __nv_bfloat16* gsrc) {
        const uint4* g4 = (const uint4*)gsrc;
        #pragma unroll
        for (int t = tid; t < 1024; t += 512) {
            int r = t >> 3, c = t & 7;
            cp16(sbase + (r*72 + c*8)*2, g4 + t);
        }
    };

    // ---- prolog
    {
        const uint4* Qg4 = (const uint4*)(g_Qbf + ((size_t)bh * L_ + i0) * D_);
        for (int t = tid; t < 1024; t += 512) {
            int r = t >> 3, c = t & 7;
            *(uint4*)(Qs + r*72 + c*8) = Qg4[t];
        }
    }
    cp_tile(ks_s[0], g_Kbf + (size_t)bh * L_ * D_);
    cp_tile(ws_s[1], g_Wpbf + (size_t)rbase0 * D_);
    cp_tile(ws_s[0], g_Wpbf + (size_t)(rbase0 + 128) * D_);
    CP_COMMIT();
    if (tid < 128) {
        wbn[128 + tid] = Wpb[rbase0 + tid] * LOG2E;
        wbn[tid]       = Wpb[rbase0 + 128 + tid] * LOG2E;
    }
    asm volatile("cp.async.wait_group 0;" ::: "memory");
    __syncthreads();

    const uint32_t qa0 = ldsm_a_addr(Qs, wr*32, lane);
    const uint32_t qa1 = qa0 + 16*72*2;
    const uint32_t boff = ((((lane >> 4) & 1)*8 + (lane & 7))*72 + ((lane >> 3) & 1)*8)*2;
    const uint32_t bline = wc*32*72*2;

    float accP[2][4][4];
    float accS[2][4][4];
    float rs[4] = {0.f, 0.f, 0.f, 0.f};

    auto pblock_mma = [&](uint32_t ws_base) {
        #pragma unroll
        for (int mf = 0; mf < 2; mf++)
            #pragma unroll
            for (int nf = 0; nf < 4; nf++)
                #pragma unroll
                for (int k = 0; k < 4; k++) accP[mf][nf][k] = 0.f;
        const uint32_t wb0a = ws_base + bline + boff;
        const uint32_t wb1a = wb0a + 16*72*2;
        #pragma unroll
        for (int kk = 0; kk < 4; kk++) {
            uint32_t a0[4], a1[4], b0v[4], b1v[4];
            ldsm_x4(a0, qa0 + kk*32);
            ldsm_x4(a1, qa1 + kk*32);
            ldsm_x4(b0v, wb0a + kk*32);
            ldsm_x4(b1v, wb1a + kk*32);
            mma16816(accP[0][0], a0, b0v[0], b0v[1]);
            mma16816(accP[0][1], a0, b0v[2], b0v[3]);
            mma16816(accP[0][2], a0, b1v[0], b1v[1]);
            mma16816(accP[0][3], a0, b1v[2], b1v[3]);
            mma16816(accP[1][0], a1, b0v[0], b0v[1]);
            mma16816(accP[1][1], a1, b0v[2], b0v[3]);
            mma16816(accP[1][2], a1, b1v[0], b1v[1]);
            mma16816(accP[1][3], a1, b1v[2], b1v[3]);
        }
    };
    auto ring_store = [&](const float* wb, int slot) {
        int pb = slot * 128;
        #pragma unroll
        for (int mf = 0; mf < 2; mf++) {
            int r0 = wr*32 + mf*16 + g, r1 = r0 + 8;
            #pragma unroll
            for (int nf = 0; nf < 4; nf++) {
                int c = wc*32 + nf*8 + qd*2;
                float b0 = wb[c], b1 = wb[c+1];
                __nv_bfloat162 v0 = cvt2(accP[mf][nf][0] + b0, accP[mf][nf][1] + b1);
                __nv_bfloat162 v1 = cvt2(accP[mf][nf][2] + b0, accP[mf][nf][3] + b1);
                *(__nv_bfloat162*)&Psm[r0*PSP + pb + c] = v0;
                *(__nv_bfloat162*)&Psm[r1*PSP + pb + c] = v1;
                if (slot == 0) {
                    *(__nv_bfloat162*)&Psm[r0*PSP + 384 + c] = v0;
                    *(__nv_bfloat162*)&Psm[r1*PSP + 384 + c] = v1;
                }
            }
        }
    };
    auto smma = [&](uint32_t ks_base) {
        #pragma unroll
        for (int mf = 0; mf < 2; mf++)
            #pragma unroll
            for (int nf = 0; nf < 4; nf++)
                #pragma unroll
                for (int k = 0; k < 4; k++) accS[mf][nf][k] = 0.f;
        const uint32_t kb0a = ks_base + bline + boff;
        const uint32_t kb1a = kb0a + 16*72*2;
        #pragma unroll
        for (int kk = 0; kk < 4; kk++) {
            uint32_t a0[4], a1[4], b0v[4], b1v[4];
            ldsm_x4(a0, qa0 + kk*32);
            ldsm_x4(a1, qa1 + kk*32);
            ldsm_x4(b0v, kb0a + kk*32);
            ldsm_x4(b1v, kb1a + kk*32);
            mma16816(accS[0][0], a0, b0v[0], b0v[1]);
            mma16816(accS[0][1], a0, b0v[2], b0v[3]);
            mma16816(accS[0][2], a0, b1v[0], b1v[1]);
            mma16816(accS[0][3], a0, b1v[2], b1v[3]);
            mma16816(accS[1][0], a1, b0v[0], b0v[1]);
            mma16816(accS[1][1], a1, b0v[2], b0v[3]);
            mma16816(accS[1][2], a1, b1v[0], b1v[1]);
            mma16816(accS[1][3], a1, b1v[2], b1v[3]);
        }
    };
    auto epilogue = [&](int psig, bool dt) {
        int off = psig*128 + 127;
        #pragma unroll
        for (int mf = 0; mf < 2; mf++) {
            int r0 = wr*32 + mf*16 + g, r1 = r0 + 8;
            const __nv_bfloat16* base0 = Psm + r0*PSP + off - r0;
            const __nv_bfloat16* base1 = Psm + r1*PSP + off - r1;
            #pragma unroll
            for (int nf = 0; nf < 4; nf++) {
                int j = wc*32 + nf*8 + qd*2;
                float t00 = accS[mf][nf][0] + __bfloat162float(base0[j]);
                float t01 = accS[mf][nf][1] + __bfloat162float(base0[j+1]);
                float t10 = accS[mf][nf][2] + __bfloat162float(base1[j]);
                float t11 = accS[mf][nf][3] + __bfloat162float(base1[j+1]);
                rs[mf*2+0] += fast_exp2(t00) + fast_exp2(t01);
                rs[mf*2+1] += fast_exp2(t10) + fast_exp2(t11);
                if (dt) {
                    if (j == r0)          sdArr[r0] = t00;
                    else if (j + 1 == r0) sdArr[r0] = t01;
                    if (j == r1)          sdArr[r1] = t10;
                    else if (j + 1 == r1) sdArr[r1] = t11;
                }
            }
        }
    };

    int sigma = (rbase0 >> 7) % 3;
    // prolog P block (slot sigma) from ws[1]
    pblock_mma(ws_s[1]);
    ring_store(wbn + 128, sigma);

    int psig = sigma;

    for (int jt = 0; jt < 16; jt++) {
        int cur = jt & 1, nxt = cur ^ 1;
        int s_w = sigma + 1; if (s_w == 3) s_w = 0;

        asm volatile("cp.async.wait_group 0;" ::: "memory");
        __syncthreads();   // buffers(jt) visible; prior reads done (WAR for cp below)

        if (jt < 15) {
            if (tid < 128) {
                int idx = rbase0 + (jt+2)*128 + tid;
                wbn[nxt*128 + tid] = (idx < 2*L_ - 1) ? Wpb[idx] * LOG2E : 0.f;
            }
            cp_tile(ks_s[nxt], g_Kbf + ((size_t)bh * L_ + (jt+1)*128) * D_);
            cp_tile(ws_s[nxt], g_Wpbf + (size_t)(rbase0 + (jt+2)*128) * D_);
            CP_COMMIT();
        }

        pblock_mma(ws_s[cur]);                 // tensor
        if (jt > 0) epilogue(psig, (jt-1) == it);   // MUFU/LDS overlaps MMA cross-warp
        smma(ks_s[cur]);                       // tensor
        ring_store(wbn + cur*128, s_w);        // STS (slot disjoint from epilogue reads)

        psig = sigma; sigma = s_w;
    }

    __syncthreads();
    epilogue(psig, it == 15);

    #pragma unroll
    for (int k = 0; k < 4; k++) {
        rs[k] += __shfl_xor_sync(0xffffffffu, rs[k], 1);
        rs[k] += __shfl_xor_sync(0xffffffffu, rs[k], 2);
    }
    if (qd == 0) {
        int base = wc*128 + wr*32 + g;
        red[base]      = rs[0];
        red[base + 8]  = rs[1];
        red[base + 16] = rs[2];
        red[base + 24] = rs[3];
    }
    __syncthreads();
    if (tid < 128) {
        float r = red[tid] + red[128 + tid] + red[256 + tid] + red[384 + tid];
        g_Diag[(size_t)bh * L_ + i0 + tid] = fast_exp2(sdArr[tid]) / r;
    }
}

// ---------------- Kernel 3: O projection, reg-prefetch pipeline, fused diag*V ---
__global__ __launch_bounds__(256, 2)
void gemm_out_bf16(const float* __restrict__ Wo, const float* __restrict__ bo,
                   float* __restrict__ out)
{
    __shared__ __nv_bfloat16 Ab[2][128*KP];
    __shared__ __nv_bfloat16 Wb[2][128*KP];

    const int m0 = blockIdx.y * 128, n0 = blockIdx.x * 128;
    const int tid = threadIdx.x, lane = tid & 31, w = tid >> 5;
    const int wr = w >> 1, wc = w & 1, g = lane >> 2, qd = lane & 3;
    const int rr = tid >> 3;
    const int c4 = (tid & 7) * 4;

    const int bq = m0 >> 11, l0 = m0 & (L_ - 1);

    float4 ra[4], rw[4];
    float dgv[4];
    auto ldg_chunk = [&](int kc) {
        int h = kc >> 1;
        const float* Ag = g_V + ((size_t)(bq*NH + h) * L_ + l0) * D_ + (kc & 1)*32;
        const float* Wg = Wo + (size_t)n0 * H_ + kc*32;
        const float* Dg = g_Diag + (size_t)(bq*NH + h) * L_ + l0;
        #pragma unroll
        for (int i = 0; i < 4; i++) {
            int r = i*32 + rr;
            ra[i]  = *(const float4*)&Ag[(size_t)r * D_ + c4];
            rw[i]  = *(const float4*)&Wg[(size_t)r * H_ + c4];
            dgv[i] = Dg[r];
        }
    };
    auto sts_chunk = [&](int buf) {
        #pragma unroll
        for (int i = 0; i < 4; i++) {
            int r = i*32 + rr;
            float d = dgv[i];
            __nv_bfloat162* pa = (__nv_bfloat162*)(Ab[buf] + r*KP + c4);
            pa[0] = cvt2(ra[i].x*d, ra[i].y*d);
            pa[1] = cvt2(ra[i].z*d, ra[i].w*d);
            __nv_bfloat162* pw = (__nv_bfloat162*)(Wb[buf] + r*KP + c4);
            pw[0] = cvt2(rw[i].x, rw[i].y);
            pw[1] = cvt2(rw[i].z, rw[i].w);
        }
    };

    uint32_t qaA[2], wbaA[2];
    #pragma unroll
    for (int b = 0; b < 2; b++) {
        qaA[b]  = smem_u32(Ab[b] + (wr*32 + (lane & 15))*KP + ((lane >> 4) & 1)*8);
        wbaA[b] = smem_u32(Wb[b] + (wc*64 + ((lane >> 4) & 1)*8 + (lane & 7))*KP
                           + ((lane >> 3) & 1)*8);
    }

    float acc[2][8][4] = {};

    ldg_chunk(0);
    sts_chunk(0);
    ldg_chunk(1);

    for (int kc = 0; kc < 16; kc++) {
        int cur = kc & 1;
        __syncthreads();
        #pragma unroll
        for (int kk = 0; kk < 2; kk++) {
            uint32_t a0[4], a1[4];
            ldsm_x4(a0, qaA[cur] + kk*32);
            ldsm_x4(a1, qaA[cur] + 16*KP*2 + kk*32);
            #pragma unroll
            for (int p = 0; p < 4; p++) {
                uint32_t bb[4];
                ldsm_x4(bb, wbaA[cur] + p*(16*KP*2) + kk*32);
                mma16816(acc[0][2*p+0], a0, bb[0], bb[1]);
                mma16816(acc[0][2*p+1], a0, bb[2], bb[3]);
                mma16816(acc[1][2*p+0], a1, bb[0], bb[1]);
                mma16816(acc[1][2*p+1], a1, bb[2], bb[3]);
            }
        }
        if (kc < 15) {
            sts_chunk(cur ^ 1);
            if (kc < 14) ldg_chunk(kc + 2);
        }
    }

    #pragma unroll
    for (int mf = 0; mf < 2; mf++) {
        int rg = m0 + wr*32 + mf*16 + g;
        #pragma unroll
        for (int nf = 0; nf < 8; nf++) {
            int n = n0 + wc*64 + nf*8 + qd*2;
            float b0 = bo[n], b1 = bo[n+1];
            *(float2*)(out + (size_t)rg * H_ + n) =
                make_float2(acc[mf][nf][0] + b0, acc[mf][nf][1] + b1);
            *(float2*)(out + (size_t)(rg + 8) * H_ + n) =
                make_float2(acc[mf][nf][2] + b0, acc[mf][nf][3] + b1);
        }
    }
}

// ---------------- launch --------------------------------------------------------
extern "C" void kernel_launch(void* const* d_in, const int* in_sizes, int n_in,
                              void* d_out, int out_size)
{
    const float* q_in = (const float*)d_in[0];
    const float* k_in = (const float*)d_in[1];
    const float* v_in = (const float*)d_in[2];
    const float* Wq_w = (const float*)d_in[3];
    const float* Wq_b = (const float*)d_in[4];
    const float* Wk_w = (const float*)d_in[5];
    const float* Wk_b = (const float*)d_in[6];
    const float* Wv_w = (const float*)d_in[7];
    const float* Wv_b = (const float*)d_in[8];
    const float* Wo_w = (const float*)d_in[9];
    const float* Wo_b = (const float*)d_in[10];
    const float* Wp_w = (const float*)d_in[11];
    const float* Wp_b = (const float*)d_in[12];

    cudaFuncSetAttribute(attn_mma_kernel,
                         cudaFuncAttributeMaxDynamicSharedMemorySize, ATT_SMEM);

    gemm_qkv_bf16<<<dim3(H_/128, (B_*L_)/128, 4), 256>>>(
        q_in, k_in, v_in, Wq_w, Wq_b, Wk_w, Wk_b, Wv_w, Wv_b, Wp_w);

    attn_mma_kernel<<<dim3(L_/128, B_*NH), 512, ATT_SMEM>>>(Wp_b);

    gemm_out_bf16<<<dim3(H_/128, (B_*L_)/128), 256>>>(Wo_w, Wo_b, (float*)d_out);
}

// round 11
// speedup vs baseline: 1.7215x; 1.0270x over previous
#include <cuda_runtime.h>
#include <cuda_bf16.h>
#include <cstdint>

#define B_  4
#define L_  2048
#define H_  512
#define NH  8
#define D_  64
#define KP  40
#define QKP 40
#define LOG2E 1.4426950408889634f

// ---------------- scratch (static device globals; no allocation) ----------------
__device__ __nv_bfloat16 g_Abf[3*B_*L_*H_];    // bf16 q_in|k_in|v_in
__device__ __nv_bfloat16 g_Wbf[3*H_*H_];       // bf16 Wq|Wk|Wv
__device__ __nv_bfloat16 g_Qbf[B_*NH*L_*D_];   // (b,h,l,d), scaled by 0.125*log2e
__device__ __nv_bfloat16 g_Kbf[B_*NH*L_*D_];
__device__ __nv_bfloat16 g_Wpbf[4096*D_];      // rows >= 4095 zero-padded
__device__ float g_V[B_*NH*L_*D_];             // fp32 head layout
__device__ float g_Diag[B_*NH*L_];
__device__ float g_RS0[B_*NH*L_];              // partial sum, j-half 0
__device__ float g_RS1[B_*NH*L_];              // partial sum, j-half 1
__device__ float g_SD[B_*NH*L_];               // diagonal score

__device__ __forceinline__ float fast_exp2(float x) {
    float y; asm("ex2.approx.f32 %0, %1;" : "=f"(y) : "f"(x)); return y;
}
__device__ __forceinline__ void mma16816(float* c, const uint32_t* a,
                                         uint32_t b0, uint32_t b1) {
    asm volatile(
        "mma.sync.aligned.m16n8k16.row.col.f32.bf16.bf16.f32 "
        "{%0,%1,%2,%3}, {%4,%5,%6,%7}, {%8,%9}, {%0,%1,%2,%3};"
        : "+f"(c[0]), "+f"(c[1]), "+f"(c[2]), "+f"(c[3])
        : "r"(a[0]), "r"(a[1]), "r"(a[2]), "r"(a[3]), "r"(b0), "r"(b1));
}
__device__ __forceinline__ void ldsm_x4(uint32_t* r, uint32_t addr) {
    asm volatile("ldmatrix.sync.aligned.m8n8.x4.shared.b16 {%0,%1,%2,%3}, [%4];"
        : "=r"(r[0]), "=r"(r[1]), "=r"(r[2]), "=r"(r[3]) : "r"(addr));
}
__device__ __forceinline__ uint32_t smem_u32(const void* p) {
    uint32_t a;
    asm("{ .reg .u64 t; cvta.to.shared.u64 t, %1; cvt.u32.u64 %0, t; }" : "=r"(a) : "l"(p));
    return a;
}
__device__ __forceinline__ void cp16(uint32_t s, const void* g) {
    asm volatile("cp.async.cg.shared.global [%0], [%1], 16;" :: "r"(s), "l"(g));
}
#define CP_COMMIT() asm volatile("cp.async.commit_group;" ::: "memory")

__device__ __forceinline__ __nv_bfloat162 cvt2(float x, float y) {
    return __halves2bfloat162(__float2bfloat16(x), __float2bfloat16(y));
}
__device__ __forceinline__ uint32_t ldsm_a_addr(const __nv_bfloat16* base, int rb, int lane) {
    return smem_u32(base + (rb + (lane & 15))*72 + ((lane >> 4) & 1)*8);
}

// ---------------- Kernel 0: convert inputs/weights/Wp to bf16 -------------------
__global__ __launch_bounds__(256)
void convert_kernel(const float* __restrict__ q, const float* __restrict__ k,
                    const float* __restrict__ v,
                    const float* __restrict__ wq, const float* __restrict__ wk,
                    const float* __restrict__ wv, const float* __restrict__ wp)
{
    const int ACT4 = (B_*L_*H_)/4;   // 1048576
    const int WT4  = (H_*H_)/4;      // 65536
    int i4 = blockIdx.x*256 + threadIdx.x;
    if (i4 < 3*ACT4) {
        int seg = i4 / ACT4, off = (i4 - seg*ACT4)*4;
        const float* s = seg == 0 ? q : (seg == 1 ? k : v);
        float4 val = *(const float4*)(s + off);
        __nv_bfloat162* d = (__nv_bfloat162*)(g_Abf + (size_t)seg*(B_*L_*H_) + off);
        d[0] = cvt2(val.x, val.y); d[1] = cvt2(val.z, val.w);
    } else if (i4 < 3*ACT4 + 3*WT4) {
        int j = i4 - 3*ACT4, seg = j / WT4, off = (j - seg*WT4)*4;
        const float* s = seg == 0 ? wq : (seg == 1 ? wk : wv);
        float4 val = *(const float4*)(s + off);
        __nv_bfloat162* d = (__nv_bfloat162*)(g_Wbf + seg*(H_*H_) + off);
        d[0] = cvt2(val.x, val.y); d[1] = cvt2(val.z, val.w);
    } else {
        int off = (i4 - 3*ACT4 - 3*WT4)*4;    // < 262144
        int r = off >> 6;
        float4 val = make_float4(0.f, 0.f, 0.f, 0.f);
        if (r < 2*L_ - 1) val = *(const float4*)(wp + off);
        __nv_bfloat162* d = (__nv_bfloat162*)(g_Wpbf + off);
        d[0] = cvt2(val.x, val.y); d[1] = cvt2(val.z, val.w);
    }
}

// ---------------- Kernel 1: QKV projections, 3-stage cp.async bf16 GEMM ---------
#define QKV_SMEM (6*128*QKP*2)    // 61440 B

__global__ __launch_bounds__(256, 2)
void gemm_qkv_bf16(const float* __restrict__ bq, const float* __restrict__ bk,
                   const float* __restrict__ bv)
{
    extern __shared__ __nv_bfloat16 qsm[];
    int mode = blockIdx.z;
    const __nv_bfloat16* A = g_Abf + (size_t)mode*(B_*L_*H_);
    const __nv_bfloat16* W = g_Wbf + mode*(H_*H_);
    const float* bias = mode == 0 ? bq : (mode == 1 ? bk : bv);

    const int m0 = blockIdx.y * 128, n0 = blockIdx.x * 128;
    const int tid = threadIdx.x, lane = tid & 31, w = tid >> 5;
    const int wr = w >> 1, wc = w & 1, g = lane >> 2, qd = lane & 3;

    __nv_bfloat16* Abuf[3]; __nv_bfloat16* Wbuf[3];
    #pragma unroll
    for (int b = 0; b < 3; b++) {
        Abuf[b] = qsm + b*2*128*QKP;
        Wbuf[b] = Abuf[b] + 128*QKP;
    }

    auto cp_chunk = [&](int kc) {
        int b = kc % 3;
        uint32_t as = smem_u32(Abuf[b]);
        uint32_t ws = smem_u32(Wbuf[b]);
        const __nv_bfloat16* Ag = A + (size_t)m0 * H_ + kc*32;
        const __nv_bfloat16* Wg = W + (size_t)n0 * H_ + kc*32;
        #pragma unroll
        for (int t = tid; t < 512; t += 256) {
            int r = t >> 2, c = (t & 3) * 8;
            cp16(as + (r*QKP + c)*2, Ag + (size_t)r * H_ + c);
            cp16(ws + (r*QKP + c)*2, Wg + (size_t)r * H_ + c);
        }
        CP_COMMIT();
    };

    uint32_t qaA[3], wbaA[3];
    #pragma unroll
    for (int b = 0; b < 3; b++) {
        qaA[b]  = smem_u32(Abuf[b] + (wr*32 + (lane & 15))*QKP + ((lane >> 4) & 1)*8);
        wbaA[b] = smem_u32(Wbuf[b] + (wc*64 + ((lane >> 4) & 1)*8 + (lane & 7))*QKP
                           + ((lane >> 3) & 1)*8);
    }

    float acc[2][8][4] = {};

    cp_chunk(0);
    cp_chunk(1);

    for (int kc = 0; kc < 16; kc++) {
        if (kc < 15) asm volatile("cp.async.wait_group 1;" ::: "memory");
        else         asm volatile("cp.async.wait_group 0;" ::: "memory");
        __syncthreads();
        if (kc < 14) cp_chunk(kc + 2);

        int b = kc % 3;
        #pragma unroll
        for (int kk = 0; kk < 2; kk++) {
            uint32_t a0[4], a1[4];
            ldsm_x4(a0, qaA[b] + kk*32);
            ldsm_x4(a1, qaA[b] + 16*QKP*2 + kk*32);
            #pragma unroll
            for (int p = 0; p < 4; p++) {
                uint32_t bb[4];
                ldsm_x4(bb, wbaA[b] + p*(16*QKP*2) + kk*32);
                mma16816(acc[0][2*p+0], a0, bb[0], bb[1]);
                mma16816(acc[0][2*p+1], a0, bb[2], bb[3]);
                mma16816(acc[1][2*p+0], a1, bb[0], bb[1]);
                mma16816(acc[1][2*p+1], a1, bb[2], bb[3]);
            }
        }
    }

    const float qs = 0.125f * LOG2E;
    #pragma unroll
    for (int mf = 0; mf < 2; mf++) {
        int rg = m0 + wr*32 + mf*16 + g;
        int b = rg >> 11, l = rg & (L_ - 1);
        #pragma unroll
        for (int nf = 0; nf < 8; nf++) {
            int n = n0 + wc*64 + nf*8 + qd*2;
            int h = n >> 6, d = n & 63;
            float b0 = bias[n], b1 = bias[n+1];
            float v00 = acc[mf][nf][0] + b0, v01 = acc[mf][nf][1] + b1;
            float v10 = acc[mf][nf][2] + b0, v11 = acc[mf][nf][3] + b1;
            size_t o0 = ((size_t)(b*NH + h) * L_ + l) * D_ + d;
            size_t o1 = o0 + 8*D_;
            if (mode == 0) {
                *(__nv_bfloat162*)(g_Qbf + o0) = cvt2(v00*qs, v01*qs);
                *(__nv_bfloat162*)(g_Qbf + o1) = cvt2(v10*qs, v11*qs);
            } else if (mode == 1) {
                *(__nv_bfloat162*)(g_Kbf + o0) = cvt2(v00, v01);
                *(__nv_bfloat162*)(g_Kbf + o1) = cvt2(v10, v11);
            } else {
                *(float2*)(g_V + o0) = make_float2(v00, v01);
                *(float2*)(g_V + o1) = make_float2(v10, v11);
            }
        }
    }
}

// ---------------- Kernel 2: HMMA score pass, j-split halves ---------------------
#define PSP 520
#define AOFF_KS0 18432
#define AOFF_KS1 36864
#define AOFF_WS0 55296
#define AOFF_WS1 73728
#define AOFF_PS  92160
#define AOFF_WB  225280
#define AOFF_SD  226304
#define AOFF_RED 226816
#define ATT_SMEM 228864

__global__ __launch_bounds__(512, 1)
void attn_mma_kernel(const float* __restrict__ Wpb)
{
    extern __shared__ char smc[];
    __nv_bfloat16* Qs  = (__nv_bfloat16*)(smc);
    __nv_bfloat16* Psm = (__nv_bfloat16*)(smc + AOFF_PS);
    float* wbn   = (float*)(smc + AOFF_WB);
    float* sdArr = (float*)(smc + AOFF_SD);
    float* red   = (float*)(smc + AOFF_RED);

    const int tid = threadIdx.x;
    const int lane = tid & 31, w = tid >> 5;
    const int wr = w >> 2, wc = w & 3;
    const int g = lane >> 2, qd = lane & 3;
    const int bh = blockIdx.y, it = blockIdx.x;
    const int half = blockIdx.z;
    const int js = half * 8;
    const int i0 = it * 128;
    const int rbase0 = 1920 - 128*it;

    const uint32_t ks_s[2] = { smem_u32(smc + AOFF_KS0), smem_u32(smc + AOFF_KS1) };
    const uint32_t ws_s[2] = { smem_u32(smc + AOFF_WS0), smem_u32(smc + AOFF_WS1) };

    auto cp_tile = [&](uint32_t sbase, const __nv_bfloat16* gsrc) {
        const uint4* g4 = (const uint4*)gsrc;
        #pragma unroll
        for (int t = tid; t < 1024; t += 512) {
            int r = t >> 3, c = t & 7;
            cp16(sbase + (r*72 + c*8)*2, g4 + t);
        }
    };

    // ---- prolog
    {
        const uint4* Qg4 = (const uint4*)(g_Qbf + ((size_t)bh * L_ + i0) * D_);
        for (int t = tid; t < 1024; t += 512) {
            int r = t >> 3, c = t & 7;
            *(uint4*)(Qs + r*72 + c*8) = Qg4[t];
        }
    }
    cp_tile(ks_s[0], g_Kbf + ((size_t)bh * L_ + js*128) * D_);
    cp_tile(ws_s[1], g_Wpbf + (size_t)(rbase0 + js*128) * D_);
    cp_tile(ws_s[0], g_Wpbf + (size_t)(rbase0 + (js+1)*128) * D_);
    CP_COMMIT();
    if (tid < 128) {
        int ia = rbase0 + js*128 + tid;
        int ib = rbase0 + (js+1)*128 + tid;
        wbn[128 + tid] = (ia < 2*L_ - 1) ? Wpb[ia] * LOG2E : 0.f;
        wbn[tid]       = (ib < 2*L_ - 1) ? Wpb[ib] * LOG2E : 0.f;
    }
    asm volatile("cp.async.wait_group 0;" ::: "memory");
    __syncthreads();

    const uint32_t qa0 = ldsm_a_addr(Qs, wr*32, lane);
    const uint32_t qa1 = qa0 + 16*72*2;
    const uint32_t boff = ((((lane >> 4) & 1)*8 + (lane & 7))*72 + ((lane >> 3) & 1)*8)*2;
    const uint32_t bline = wc*32*72*2;

    float accP[2][4][4];
    float accS[2][4][4];
    float rs[4] = {0.f, 0.f, 0.f, 0.f};

    auto pblock_mma = [&](uint32_t ws_base) {
        #pragma unroll
        for (int mf = 0; mf < 2; mf++)
            #pragma unroll
            for (int nf = 0; nf < 4; nf++)
                #pragma unroll
                for (int k = 0; k < 4; k++) accP[mf][nf][k] = 0.f;
        const uint32_t wb0a = ws_base + bline + boff;
        const uint32_t wb1a = wb0a + 16*72*2;
        #pragma unroll
        for (int kk = 0; kk < 4; kk++) {
            uint32_t a0[4], a1[4], b0v[4], b1v[4];
            ldsm_x4(a0, qa0 + kk*32);
            ldsm_x4(a1, qa1 + kk*32);
            ldsm_x4(b0v, wb0a + kk*32);
            ldsm_x4(b1v, wb1a + kk*32);
            mma16816(accP[0][0], a0, b0v[0], b0v[1]);
            mma16816(accP[0][1], a0, b0v[2], b0v[3]);
            mma16816(accP[0][2], a0, b1v[0], b1v[1]);
            mma16816(accP[0][3], a0, b1v[2], b1v[3]);
            mma16816(accP[1][0], a1, b0v[0], b0v[1]);
            mma16816(accP[1][1], a1, b0v[2], b0v[3]);
            mma16816(accP[1][2], a1, b1v[0], b1v[1]);
            mma16816(accP[1][3], a1, b1v[2], b1v[3]);
        }
    };
    auto ring_store = [&](const float* wb, int slot) {
        int pb = slot * 128;
        #pragma unroll
        for (int mf = 0; mf < 2; mf++) {
            int r0 = wr*32 + mf*16 + g, r1 = r0 + 8;
            #pragma unroll
            for (int nf = 0; nf < 4; nf++) {
                int c = wc*32 + nf*8 + qd*2;
                float b0 = wb[c], b1 = wb[c+1];
                __nv_bfloat162 v0 = cvt2(accP[mf][nf][0] + b0, accP[mf][nf][1] + b1);
                __nv_bfloat162 v1 = cvt2(accP[mf][nf][2] + b0, accP[mf][nf][3] + b1);
                *(__nv_bfloat162*)&Psm[r0*PSP + pb + c] = v0;
                *(__nv_bfloat162*)&Psm[r1*PSP + pb + c] = v1;
                if (slot == 0) {
                    *(__nv_bfloat162*)&Psm[r0*PSP + 384 + c] = v0;
                    *(__nv_bfloat162*)&Psm[r1*PSP + 384 + c] = v1;
                }
            }
        }
    };
    auto smma = [&](uint32_t ks_base) {
        #pragma unroll
        for (int mf = 0; mf < 2; mf++)
            #pragma unroll
            for (int nf = 0; nf < 4; nf++)
                #pragma unroll
                for (int k = 0; k < 4; k++) accS[mf][nf][k] = 0.f;
        const uint32_t kb0a = ks_base + bline + boff;
        const uint32_t kb1a = kb0a + 16*72*2;
        #pragma unroll
        for (int kk = 0; kk < 4; kk++) {
            uint32_t a0[4], a1[4], b0v[4], b1v[4];
            ldsm_x4(a0, qa0 + kk*32);
            ldsm_x4(a1, qa1 + kk*32);
            ldsm_x4(b0v, kb0a + kk*32);
            ldsm_x4(b1v, kb1a + kk*32);
            mma16816(accS[0][0], a0, b0v[0], b0v[1]);
            mma16816(accS[0][1], a0, b0v[2], b0v[3]);
            mma16816(accS[0][2], a0, b1v[0], b1v[1]);
            mma16816(accS[0][3], a0, b1v[2], b1v[3]);
            mma16816(accS[1][0], a1, b0v[0], b0v[1]);
            mma16816(accS[1][1], a1, b0v[2], b0v[3]);
            mma16816(accS[1][2], a1, b1v[0], b1v[1]);
            mma16816(accS[1][3], a1, b1v[2], b1v[3]);
        }
    };
    auto epilogue = [&](int psig, bool dt) {
        int off = psig*128 + 127;
        #pragma unroll
        for (int mf = 0; mf < 2; mf++) {
            int r0 = wr*32 + mf*16 + g, r1 = r0 + 8;
            const __nv_bfloat16* base0 = Psm + r0*PSP + off - r0;
            const __nv_bfloat16* base1 = Psm + r1*PSP + off - r1;
            #pragma unroll
            for (int nf = 0; nf < 4; nf++) {
                int j = wc*32 + nf*8 + qd*2;
                float t00 = accS[mf][nf][0] + __bfloat162float(base0[j]);
                float t01 = accS[mf][nf][1] + __bfloat162float(base0[j+1]);
                float t10 = accS[mf][nf][2] + __bfloat162float(base1[j]);
                float t11 = accS[mf][nf][3] + __bfloat162float(base1[j+1]);
                rs[mf*2+0] += fast_exp2(t00) + fast_exp2(t01);
                rs[mf*2+1] += fast_exp2(t10) + fast_exp2(t11);
                if (dt) {
                    if (j == r0)          sdArr[r0] = t00;
                    else if (j + 1 == r0) sdArr[r0] = t01;
                    if (j == r1)          sdArr[r1] = t10;
                    else if (j + 1 == r1) sdArr[r1] = t11;
                }
            }
        }
    };

    int sigma = (((rbase0 >> 7) + js)) % 3;
    pblock_mma(ws_s[1]);
    ring_store(wbn + 128, sigma);

    int psig = sigma;

    for (int jt = js; jt < js + 8; jt++) {
        int t = jt - js;
        int cur = t & 1, nxt = cur ^ 1;
        int s_w = sigma + 1; if (s_w == 3) s_w = 0;

        asm volatile("cp.async.wait_group 0;" ::: "memory");
        __syncthreads();

        if (t < 7) {
            if (tid < 128) {
                int idx = rbase0 + (jt+2)*128 + tid;
                wbn[nxt*128 + tid] = (idx < 2*L_ - 1) ? Wpb[idx] * LOG2E : 0.f;
            }
            cp_tile(ks_s[nxt], g_Kbf + ((size_t)bh * L_ + (jt+1)*128) * D_);
            cp_tile(ws_s[nxt], g_Wpbf + (size_t)(rbase0 + (jt+2)*128) * D_);
            CP_COMMIT();
        }

        pblock_mma(ws_s[cur]);
        if (t > 0) epilogue(psig, (jt-1) == it);
        smma(ks_s[cur]);
        ring_store(wbn + cur*128, s_w);

        psig = sigma; sigma = s_w;
    }

    __syncthreads();
    epilogue(psig, (js + 7) == it);

    #pragma unroll
    for (int k = 0; k < 4; k++) {
        rs[k] += __shfl_xor_sync(0xffffffffu, rs[k], 1);
        rs[k] += __shfl_xor_sync(0xffffffffu, rs[k], 2);
    }
    if (qd == 0) {
        int base = wc*128 + wr*32 + g;
        red[base]      = rs[0];
        red[base + 8]  = rs[1];
        red[base + 16] = rs[2];
        red[base + 24] = rs[3];
    }
    __syncthreads();
    if (tid < 128) {
        float r = red[tid] + red[128 + tid] + red[256 + tid] + red[384 + tid];
        size_t o = (size_t)bh * L_ + i0 + tid;
        if (half) g_RS1[o] = r; else g_RS0[o] = r;
        if ((it >> 3) == half) g_SD[o] = sdArr[tid];
    }
}

// ---------------- Kernel 2b: combine partial softmax -> diagonal ----------------
__global__ __launch_bounds__(256)
void diag_combine()
{
    int i = blockIdx.x * 256 + threadIdx.x;    // < 65536
    g_Diag[i] = fast_exp2(g_SD[i]) / (g_RS0[i] + g_RS1[i]);
}

// ---------------- Kernel 3: O projection, reg-prefetch pipeline, fused diag*V ---
__global__ __launch_bounds__(256, 2)
void gemm_out_bf16(const float* __restrict__ Wo, const float* __restrict__ bo,
                   float* __restrict__ out)
{
    __shared__ __nv_bfloat16 Ab[2][128*KP];
    __shared__ __nv_bfloat16 Wb[2][128*KP];

    const int m0 = blockIdx.y * 128, n0 = blockIdx.x * 128;
    const int tid = threadIdx.x, lane = tid & 31, w = tid >> 5;
    const int wr = w >> 1, wc = w & 1, g = lane >> 2, qd = lane & 3;
    const int rr = tid >> 3;
    const int c4 = (tid & 7) * 4;

    const int bq = m0 >> 11, l0 = m0 & (L_ - 1);

    float4 ra[4], rw[4];
    float dgv[4];
    auto ldg_chunk = [&](int kc) {
        int h = kc >> 1;
        const float* Ag = g_V + ((size_t)(bq*NH + h) * L_ + l0) * D_ + (kc & 1)*32;
        const float* Wg = Wo + (size_t)n0 * H_ + kc*32;
        const float* Dg = g_Diag + (size_t)(bq*NH + h) * L_ + l0;
        #pragma unroll
        for (int i = 0; i < 4; i++) {
            int r = i*32 + rr;
            ra[i]  = *(const float4*)&Ag[(size_t)r * D_ + c4];
            rw[i]  = *(const float4*)&Wg[(size_t)r * H_ + c4];
            dgv[i] = Dg[r];
        }
    };
    auto sts_chunk = [&](int buf) {
        #pragma unroll
        for (int i = 0; i < 4; i++) {
            int r = i*32 + rr;
            float d = dgv[i];
            __nv_bfloat162* pa = (__nv_bfloat162*)(Ab[buf] + r*KP + c4);
            pa[0] = cvt2(ra[i].x*d, ra[i].y*d);
            pa[1] = cvt2(ra[i].z*d, ra[i].w*d);
            __nv_bfloat162* pw = (__nv_bfloat162*)(Wb[buf] + r*KP + c4);
            pw[0] = cvt2(rw[i].x, rw[i].y);
            pw[1] = cvt2(rw[i].z, rw[i].w);
        }
    };

    uint32_t qaA[2], wbaA[2];
    #pragma unroll
    for (int b = 0; b < 2; b++) {
        qaA[b]  = smem_u32(Ab[b] + (wr*32 + (lane & 15))*KP + ((lane >> 4) & 1)*8);
        wbaA[b] = smem_u32(Wb[b] + (wc*64 + ((lane >> 4) & 1)*8 + (lane & 7))*KP
                           + ((lane >> 3) & 1)*8);
    }

    float acc[2][8][4] = {};

    ldg_chunk(0);
    sts_chunk(0);
    ldg_chunk(1);

    for (int kc = 0; kc < 16; kc++) {
        int cur = kc & 1;
        __syncthreads();
        #pragma unroll
        for (int kk = 0; kk < 2; kk++) {
            uint32_t a0[4], a1[4];
            ldsm_x4(a0, qaA[cur] + kk*32);
            ldsm_x4(a1, qaA[cur] + 16*KP*2 + kk*32);
            #pragma unroll
            for (int p = 0; p < 4; p++) {
                uint32_t bb[4];
                ldsm_x4(bb, wbaA[cur] + p*(16*KP*2) + kk*32);
                mma16816(acc[0][2*p+0], a0, bb[0], bb[1]);
                mma16816(acc[0][2*p+1], a0, bb[2], bb[3]);
                mma16816(acc[1][2*p+0], a1, bb[0], bb[1]);
                mma16816(acc[1][2*p+1], a1, bb[2], bb[3]);
            }
        }
        if (kc < 15) {
            sts_chunk(cur ^ 1);
            if (kc < 14) ldg_chunk(kc + 2);
        }
    }

    #pragma unroll
    for (int mf = 0; mf < 2; mf++) {
        int rg = m0 + wr*32 + mf*16 + g;
        #pragma unroll
        for (int nf = 0; nf < 8; nf++) {
            int n = n0 + wc*64 + nf*8 + qd*2;
            float b0 = bo[n], b1 = bo[n+1];
            *(float2*)(out + (size_t)rg * H_ + n) =
                make_float2(acc[mf][nf][0] + b0, acc[mf][nf][1] + b1);
            *(float2*)(out + (size_t)(rg + 8) * H_ + n) =
                make_float2(acc[mf][nf][2] + b0, acc[mf][nf][3] + b1);
        }
    }
}

// ---------------- launch --------------------------------------------------------
extern "C" void kernel_launch(void* const* d_in, const int* in_sizes, int n_in,
                              void* d_out, int out_size)
{
    const float* q_in = (const float*)d_in[0];
    const float* k_in = (const float*)d_in[1];
    const float* v_in = (const float*)d_in[2];
    const float* Wq_w = (const float*)d_in[3];
    const float* Wq_b = (const float*)d_in[4];
    const float* Wk_w = (const float*)d_in[5];
    const float* Wk_b = (const float*)d_in[6];
    const float* Wv_w = (const float*)d_in[7];
    const float* Wv_b = (const float*)d_in[8];
    const float* Wo_w = (const float*)d_in[9];
    const float* Wo_b = (const float*)d_in[10];
    const float* Wp_w = (const float*)d_in[11];
    const float* Wp_b = (const float*)d_in[12];

    cudaFuncSetAttribute(attn_mma_kernel,
                         cudaFuncAttributeMaxDynamicSharedMemorySize, ATT_SMEM);
    cudaFuncSetAttribute(gemm_qkv_bf16,
                         cudaFuncAttributeMaxDynamicSharedMemorySize, QKV_SMEM);

    convert_kernel<<<13312, 256>>>(q_in, k_in, v_in, Wq_w, Wk_w, Wv_w, Wp_w);

    gemm_qkv_bf16<<<dim3(H_/128, (B_*L_)/128, 3), 256, QKV_SMEM>>>(Wq_b, Wk_b, Wv_b);

    attn_mma_kernel<<<dim3(L_/128, B_*NH, 2), 512, ATT_SMEM>>>(Wp_b);

    diag_combine<<<(B_*NH*L_)/256, 256>>>();

    gemm_out_bf16<<<dim3(H_/128, (B_*L_)/128), 256>>>(Wo_w, Wo_b, (float*)d_out);
}

// round 12
// speedup vs baseline: 1.8344x; 1.0656x over previous
#include <cuda_runtime.h>
#include <cuda_bf16.h>
#include <cuda_fp16.h>
#include <cstdint>

#define B_  4
#define L_  2048
#define H_  512
#define NH  8
#define D_  64
#define KP  40
#define QKP 40
#define LOG2E 1.4426950408889634f

// ---------------- scratch (static device globals; no allocation) ----------------
__device__ __nv_bfloat16 g_Abf[3*B_*L_*H_];    // bf16 q_in|k_in|v_in
__device__ __nv_bfloat16 g_Wbf[3*H_*H_];       // bf16 Wq|Wk|Wv
__device__ __nv_bfloat16 g_Qbf[B_*NH*L_*D_];   // (b,h,l,d), scaled by 0.125*log2e
__device__ __nv_bfloat16 g_Kbf[B_*NH*L_*D_];
__device__ __nv_bfloat16 g_Wpbf[4096*D_];      // rows >= 4095 zero-padded
__device__ float g_V[B_*NH*L_*D_];             // fp32 head layout
__device__ float g_RS0[B_*NH*L_];              // partial sum, j-half 0
__device__ float g_RS1[B_*NH*L_];              // partial sum, j-half 1
__device__ float g_SD[B_*NH*L_];               // diagonal score

__device__ __forceinline__ float fast_exp2(float x) {
    float y; asm("ex2.approx.f32 %0, %1;" : "=f"(y) : "f"(x)); return y;
}
__device__ __forceinline__ float fast_rcp(float x) {
    float y; asm("rcp.approx.f32 %0, %1;" : "=f"(y) : "f"(x)); return y;
}
__device__ __forceinline__ void mma16816(float* c, const uint32_t* a,
                                         uint32_t b0, uint32_t b1) {
    asm volatile(
        "mma.sync.aligned.m16n8k16.row.col.f32.bf16.bf16.f32 "
        "{%0,%1,%2,%3}, {%4,%5,%6,%7}, {%8,%9}, {%0,%1,%2,%3};"
        : "+f"(c[0]), "+f"(c[1]), "+f"(c[2]), "+f"(c[3])
        : "r"(a[0]), "r"(a[1]), "r"(a[2]), "r"(a[3]), "r"(b0), "r"(b1));
}
__device__ __forceinline__ void ldsm_x4(uint32_t* r, uint32_t addr) {
    asm volatile("ldmatrix.sync.aligned.m8n8.x4.shared.b16 {%0,%1,%2,%3}, [%4];"
        : "=r"(r[0]), "=r"(r[1]), "=r"(r[2]), "=r"(r[3]) : "r"(addr));
}
__device__ __forceinline__ uint32_t smem_u32(const void* p) {
    uint32_t a;
    asm("{ .reg .u64 t; cvta.to.shared.u64 t, %1; cvt.u32.u64 %0, t; }" : "=r"(a) : "l"(p));
    return a;
}
__device__ __forceinline__ void cp16(uint32_t s, const void* g) {
    asm volatile("cp.async.cg.shared.global [%0], [%1], 16;" :: "r"(s), "l"(g));
}
#define CP_COMMIT() asm volatile("cp.async.commit_group;" ::: "memory")

__device__ __forceinline__ __nv_bfloat162 cvt2(float x, float y) {
    return __halves2bfloat162(__float2bfloat16(x), __float2bfloat16(y));
}
__device__ __forceinline__ uint32_t ldsm_a_addr(const __nv_bfloat16* base, int rb, int lane) {
    return smem_u32(base + (rb + (lane & 15))*72 + ((lane >> 4) & 1)*8);
}
// pack two f32 to f16x2 (lo = a, hi = b), exp2 both halves, accumulate
__device__ __forceinline__ void exp2_acc_f16x2(uint32_t& hacc, float a, float b) {
    uint32_t p, e;
    asm("cvt.rn.f16x2.f32 %0, %1, %2;" : "=r"(p) : "f"(b), "f"(a));
    asm("ex2.approx.f16x2 %0, %1;" : "=r"(e) : "r"(p));
    asm("add.rn.f16x2 %0, %0, %1;" : "+r"(hacc) : "r"(e));
}

// ---------------- Kernel 0: convert inputs/weights/Wp to bf16 -------------------
__global__ __launch_bounds__(256)
void convert_kernel(const float* __restrict__ q, const float* __restrict__ k,
                    const float* __restrict__ v,
                    const float* __restrict__ wq, const float* __restrict__ wk,
                    const float* __restrict__ wv, const float* __restrict__ wp)
{
    const int ACT4 = (B_*L_*H_)/4;   // 1048576
    const int WT4  = (H_*H_)/4;      // 65536
    int i4 = blockIdx.x*256 + threadIdx.x;
    if (i4 < 3*ACT4) {
        int seg = i4 / ACT4, off = (i4 - seg*ACT4)*4;
        const float* s = seg == 0 ? q : (seg == 1 ? k : v);
        float4 val = *(const float4*)(s + off);
        __nv_bfloat162* d = (__nv_bfloat162*)(g_Abf + (size_t)seg*(B_*L_*H_) + off);
        d[0] = cvt2(val.x, val.y); d[1] = cvt2(val.z, val.w);
    } else if (i4 < 3*ACT4 + 3*WT4) {
        int j = i4 - 3*ACT4, seg = j / WT4, off = (j - seg*WT4)*4;
        const float* s = seg == 0 ? wq : (seg == 1 ? wk : wv);
        float4 val = *(const float4*)(s + off);
        __nv_bfloat162* d = (__nv_bfloat162*)(g_Wbf + seg*(H_*H_) + off);
        d[0] = cvt2(val.x, val.y); d[1] = cvt2(val.z, val.w);
    } else {
        int off = (i4 - 3*ACT4 - 3*WT4)*4;    // < 262144
        int r = off >> 6;
        float4 val = make_float4(0.f, 0.f, 0.f, 0.f);
        if (r < 2*L_ - 1) val = *(const float4*)(wp + off);
        __nv_bfloat162* d = (__nv_bfloat162*)(g_Wpbf + off);
        d[0] = cvt2(val.x, val.y); d[1] = cvt2(val.z, val.w);
    }
}

// ---------------- Kernel 1: QKV projections, 3-stage cp.async bf16 GEMM ---------
#define QKV_SMEM (6*128*QKP*2)    // 61440 B

__global__ __launch_bounds__(256, 2)
void gemm_qkv_bf16(const float* __restrict__ bq, const float* __restrict__ bk,
                   const float* __restrict__ bv)
{
    extern __shared__ __nv_bfloat16 qsm[];
    int mode = blockIdx.z;
    const __nv_bfloat16* A = g_Abf + (size_t)mode*(B_*L_*H_);
    const __nv_bfloat16* W = g_Wbf + mode*(H_*H_);
    const float* bias = mode == 0 ? bq : (mode == 1 ? bk : bv);

    const int m0 = blockIdx.y * 128, n0 = blockIdx.x * 128;
    const int tid = threadIdx.x, lane = tid & 31, w = tid >> 5;
    const int wr = w >> 1, wc = w & 1, g = lane >> 2, qd = lane & 3;

    __nv_bfloat16* Abuf[3]; __nv_bfloat16* Wbuf[3];
    #pragma unroll
    for (int b = 0; b < 3; b++) {
        Abuf[b] = qsm + b*2*128*QKP;
        Wbuf[b] = Abuf[b] + 128*QKP;
    }

    auto cp_chunk = [&](int kc) {
        int b = kc % 3;
        uint32_t as = smem_u32(Abuf[b]);
        uint32_t ws = smem_u32(Wbuf[b]);
        const __nv_bfloat16* Ag = A + (size_t)m0 * H_ + kc*32;
        const __nv_bfloat16* Wg = W + (size_t)n0 * H_ + kc*32;
        #pragma unroll
        for (int t = tid; t < 512; t += 256) {
            int r = t >> 2, c = (t & 3) * 8;
            cp16(as + (r*QKP + c)*2, Ag + (size_t)r * H_ + c);
            cp16(ws + (r*QKP + c)*2, Wg + (size_t)r * H_ + c);
        }
        CP_COMMIT();
    };

    uint32_t qaA[3], wbaA[3];
    #pragma unroll
    for (int b = 0; b < 3; b++) {
        qaA[b]  = smem_u32(Abuf[b] + (wr*32 + (lane & 15))*QKP + ((lane >> 4) & 1)*8);
        wbaA[b] = smem_u32(Wbuf[b] + (wc*64 + ((lane >> 4) & 1)*8 + (lane & 7))*QKP
                           + ((lane >> 3) & 1)*8);
    }

    float acc[2][8][4] = {};

    cp_chunk(0);
    cp_chunk(1);

    for (int kc = 0; kc < 16; kc++) {
        if (kc < 15) asm volatile("cp.async.wait_group 1;" ::: "memory");
        else         asm volatile("cp.async.wait_group 0;" ::: "memory");
        __syncthreads();
        if (kc < 14) cp_chunk(kc + 2);

        int b = kc % 3;
        #pragma unroll
        for (int kk = 0; kk < 2; kk++) {
            uint32_t a0[4], a1[4];
            ldsm_x4(a0, qaA[b] + kk*32);
            ldsm_x4(a1, qaA[b] + 16*QKP*2 + kk*32);
            #pragma unroll
            for (int p = 0; p < 4; p++) {
                uint32_t bb[4];
                ldsm_x4(bb, wbaA[b] + p*(16*QKP*2) + kk*32);
                mma16816(acc[0][2*p+0], a0, bb[0], bb[1]);
                mma16816(acc[0][2*p+1], a0, bb[2], bb[3]);
                mma16816(acc[1][2*p+0], a1, bb[0], bb[1]);
                mma16816(acc[1][2*p+1], a1, bb[2], bb[3]);
            }
        }
    }

    const float qs = 0.125f * LOG2E;
    #pragma unroll
    for (int mf = 0; mf < 2; mf++) {
        int rg = m0 + wr*32 + mf*16 + g;
        int b = rg >> 11, l = rg & (L_ - 1);
        #pragma unroll
        for (int nf = 0; nf < 8; nf++) {
            int n = n0 + wc*64 + nf*8 + qd*2;
            int h = n >> 6, d = n & 63;
            float b0 = bias[n], b1 = bias[n+1];
            float v00 = acc[mf][nf][0] + b0, v01 = acc[mf][nf][1] + b1;
            float v10 = acc[mf][nf][2] + b0, v11 = acc[mf][nf][3] + b1;
            size_t o0 = ((size_t)(b*NH + h) * L_ + l) * D_ + d;
            size_t o1 = o0 + 8*D_;
            if (mode == 0) {
                *(__nv_bfloat162*)(g_Qbf + o0) = cvt2(v00*qs, v01*qs);
                *(__nv_bfloat162*)(g_Qbf + o1) = cvt2(v10*qs, v11*qs);
            } else if (mode == 1) {
                *(__nv_bfloat162*)(g_Kbf + o0) = cvt2(v00, v01);
                *(__nv_bfloat162*)(g_Kbf + o1) = cvt2(v10, v11);
            } else {
                *(float2*)(g_V + o0) = make_float2(v00, v01);
                *(float2*)(g_V + o1) = make_float2(v10, v11);
            }
        }
    }
}

// ---------------- Kernel 2: HMMA score pass, Q-frag cached, f16x2 exp -----------
#define PSP 520
#define AOFF_KS0 18432
#define AOFF_KS1 36864
#define AOFF_WS0 55296
#define AOFF_WS1 73728
#define AOFF_PS  92160
#define AOFF_WB  225280
#define AOFF_SD  226304
#define AOFF_RED 226816
#define ATT_SMEM 228864

__global__ __launch_bounds__(512, 1)
void attn_mma_kernel(const float* __restrict__ Wpb)
{
    extern __shared__ char smc[];
    __nv_bfloat16* Qs  = (__nv_bfloat16*)(smc);
    __nv_bfloat16* Psm = (__nv_bfloat16*)(smc + AOFF_PS);
    float* wbn   = (float*)(smc + AOFF_WB);
    float* sdArr = (float*)(smc + AOFF_SD);
    float* red   = (float*)(smc + AOFF_RED);

    const int tid = threadIdx.x;
    const int lane = tid & 31, w = tid >> 5;
    const int wr = w >> 2, wc = w & 3;
    const int g = lane >> 2, qd = lane & 3;
    const int bh = blockIdx.y, it = blockIdx.x;
    const int half = blockIdx.z;
    const int js = half * 8;
    const int i0 = it * 128;
    const int rbase0 = 1920 - 128*it;

    const uint32_t ks_s[2] = { smem_u32(smc + AOFF_KS0), smem_u32(smc + AOFF_KS1) };
    const uint32_t ws_s[2] = { smem_u32(smc + AOFF_WS0), smem_u32(smc + AOFF_WS1) };

    auto cp_tile = [&](uint32_t sbase, const __nv_bfloat16* gsrc) {
        const uint4* g4 = (const uint4*)gsrc;
        #pragma unroll
        for (int t = tid; t < 1024; t += 512) {
            int r = t >> 3, c = t & 7;
            cp16(sbase + (r*72 + c*8)*2, g4 + t);
        }
    };

    // ---- prolog
    {
        const uint4* Qg4 = (const uint4*)(g_Qbf + ((size_t)bh * L_ + i0) * D_);
        for (int t = tid; t < 1024; t += 512) {
            int r = t >> 3, c = t & 7;
            *(uint4*)(Qs + r*72 + c*8) = Qg4[t];
        }
    }
    cp_tile(ks_s[0], g_Kbf + ((size_t)bh * L_ + js*128) * D_);
    cp_tile(ws_s[1], g_Wpbf + (size_t)(rbase0 + js*128) * D_);
    cp_tile(ws_s[0], g_Wpbf + (size_t)(rbase0 + (js+1)*128) * D_);
    CP_COMMIT();
    if (tid < 128) {
        int ia = rbase0 + js*128 + tid;
        int ib = rbase0 + (js+1)*128 + tid;
        wbn[128 + tid] = (ia < 2*L_ - 1) ? Wpb[ia] * LOG2E : 0.f;
        wbn[tid]       = (ib < 2*L_ - 1) ? Wpb[ib] * LOG2E : 0.f;
    }
    asm volatile("cp.async.wait_group 0;" ::: "memory");
    __syncthreads();

    // Q fragments cached for the whole kernel (Qs never rewritten)
    uint32_t qf[4][2][4];
    {
        const uint32_t qa0 = ldsm_a_addr(Qs, wr*32, lane);
        const uint32_t qa1 = qa0 + 16*72*2;
        #pragma unroll
        for (int kk = 0; kk < 4; kk++) {
            ldsm_x4(qf[kk][0], qa0 + kk*32);
            ldsm_x4(qf[kk][1], qa1 + kk*32);
        }
    }

    const uint32_t boff = ((((lane >> 4) & 1)*8 + (lane & 7))*72 + ((lane >> 3) & 1)*8)*2;
    const uint32_t bline = wc*32*72*2;

    float accP[2][2][4];   // one 16-col half at a time
    float accS[2][4][4];
    float rs[4] = {0.f, 0.f, 0.f, 0.f};

    auto pblock_half = [&](uint32_t ws_base, int h) {
        #pragma unroll
        for (int mf = 0; mf < 2; mf++)
            #pragma unroll
            for (int nf = 0; nf < 2; nf++)
                #pragma unroll
                for (int k = 0; k < 4; k++) accP[mf][nf][k] = 0.f;
        const uint32_t ba = ws_base + bline + boff + h*(16*72*2);
        #pragma unroll
        for (int kk = 0; kk < 4; kk++) {
            uint32_t bb[4];
            ldsm_x4(bb, ba + kk*32);
            mma16816(accP[0][0], qf[kk][0], bb[0], bb[1]);
            mma16816(accP[0][1], qf[kk][0], bb[2], bb[3]);
            mma16816(accP[1][0], qf[kk][1], bb[0], bb[1]);
            mma16816(accP[1][1], qf[kk][1], bb[2], bb[3]);
        }
    };
    auto store_half = [&](const float* wb, int slot, int h) {
        int pb = slot * 128;
        #pragma unroll
        for (int mf = 0; mf < 2; mf++) {
            int r0 = wr*32 + mf*16 + g, r1 = r0 + 8;
            #pragma unroll
            for (int nf = 0; nf < 2; nf++) {
                int c = wc*32 + (h*2 + nf)*8 + qd*2;
                float b0 = wb[c], b1 = wb[c+1];
                __nv_bfloat162 v0 = cvt2(accP[mf][nf][0] + b0, accP[mf][nf][1] + b1);
                __nv_bfloat162 v1 = cvt2(accP[mf][nf][2] + b0, accP[mf][nf][3] + b1);
                *(__nv_bfloat162*)&Psm[r0*PSP + pb + c] = v0;
                *(__nv_bfloat162*)&Psm[r1*PSP + pb + c] = v1;
                if (slot == 0) {
                    *(__nv_bfloat162*)&Psm[r0*PSP + 384 + c] = v0;
                    *(__nv_bfloat162*)&Psm[r1*PSP + 384 + c] = v1;
                }
            }
        }
    };
    auto smma = [&](uint32_t ks_base) {
        #pragma unroll
        for (int mf = 0; mf < 2; mf++)
            #pragma unroll
            for (int nf = 0; nf < 4; nf++)
                #pragma unroll
                for (int k = 0; k < 4; k++) accS[mf][nf][k] = 0.f;
        const uint32_t kb0a = ks_base + bline + boff;
        const uint32_t kb1a = kb0a + 16*72*2;
        #pragma unroll
        for (int kk = 0; kk < 4; kk++) {
            uint32_t b0v[4], b1v[4];
            ldsm_x4(b0v, kb0a + kk*32);
            ldsm_x4(b1v, kb1a + kk*32);
            mma16816(accS[0][0], qf[kk][0], b0v[0], b0v[1]);
            mma16816(accS[0][1], qf[kk][0], b0v[2], b0v[3]);
            mma16816(accS[0][2], qf[kk][0], b1v[0], b1v[1]);
            mma16816(accS[0][3], qf[kk][0], b1v[2], b1v[3]);
            mma16816(accS[1][0], qf[kk][1], b0v[0], b0v[1]);
            mma16816(accS[1][1], qf[kk][1], b0v[2], b0v[3]);
            mma16816(accS[1][2], qf[kk][1], b1v[0], b1v[1]);
            mma16816(accS[1][3], qf[kk][1], b1v[2], b1v[3]);
        }
    };
    auto epilogue = [&](int psig, bool dt) {
        int off = psig*128 + 127;
        uint32_t hacc[4] = {0u, 0u, 0u, 0u};
        #pragma unroll
        for (int mf = 0; mf < 2; mf++) {
            int r0 = wr*32 + mf*16 + g, r1 = r0 + 8;
            const __nv_bfloat16* base0 = Psm + r0*PSP + off - r0;
            const __nv_bfloat16* base1 = Psm + r1*PSP + off - r1;
            #pragma unroll
            for (int nf = 0; nf < 4; nf++) {
                int j = wc*32 + nf*8 + qd*2;
                float t00 = accS[mf][nf][0] + __bfloat162float(base0[j]);
                float t01 = accS[mf][nf][1] + __bfloat162float(base0[j+1]);
                float t10 = accS[mf][nf][2] + __bfloat162float(base1[j]);
                float t11 = accS[mf][nf][3] + __bfloat162float(base1[j+1]);
                exp2_acc_f16x2(hacc[mf*2+0], t00, t01);
                exp2_acc_f16x2(hacc[mf*2+1], t10, t11);
                if (dt) {
                    if (j == r0)          sdArr[r0] = t00;
                    else if (j + 1 == r0) sdArr[r0] = t01;
                    if (j == r1)          sdArr[r1] = t10;
                    else if (j + 1 == r1) sdArr[r1] = t11;
                }
            }
        }
        #pragma unroll
        for (int k = 0; k < 4; k++) {
            __half2 hv = *reinterpret_cast<__half2*>(&hacc[k]);
            rs[k] += __low2float(hv) + __high2float(hv);
        }
    };

    int sigma = (((rbase0 >> 7) + js)) % 3;
    pblock_half(ws_s[1], 0); store_half(wbn + 128, sigma, 0);
    pblock_half(ws_s[1], 1); store_half(wbn + 128, sigma, 1);

    int psig = sigma;

    for (int jt = js; jt < js + 8; jt++) {
        int t = jt - js;
        int cur = t & 1, nxt = cur ^ 1;
        int s_w = sigma + 1; if (s_w == 3) s_w = 0;

        asm volatile("cp.async.wait_group 0;" ::: "memory");
        __syncthreads();

        if (t < 7) {
            if (tid < 128) {
                int idx = rbase0 + (jt+2)*128 + tid;
                wbn[nxt*128 + tid] = (idx < 2*L_ - 1) ? Wpb[idx] * LOG2E : 0.f;
            }
            cp_tile(ks_s[nxt], g_Kbf + ((size_t)bh * L_ + (jt+1)*128) * D_);
            cp_tile(ws_s[nxt], g_Wpbf + (size_t)(rbase0 + (jt+2)*128) * D_);
            CP_COMMIT();
        }

        pblock_half(ws_s[cur], 0); store_half(wbn + cur*128, s_w, 0);
        pblock_half(ws_s[cur], 1); store_half(wbn + cur*128, s_w, 1);
        if (t > 0) epilogue(psig, (jt-1) == it);
        smma(ks_s[cur]);

        psig = sigma; sigma = s_w;
    }

    __syncthreads();
    epilogue(psig, (js + 7) == it);

    #pragma unroll
    for (int k = 0; k < 4; k++) {
        rs[k] += __shfl_xor_sync(0xffffffffu, rs[k], 1);
        rs[k] += __shfl_xor_sync(0xffffffffu, rs[k], 2);
    }
    if (qd == 0) {
        int base = wc*128 + wr*32 + g;
        red[base]      = rs[0];
        red[base + 8]  = rs[1];
        red[base + 16] = rs[2];
        red[base + 24] = rs[3];
    }
    __syncthreads();
    if (tid < 128) {
        float r = red[tid] + red[128 + tid] + red[256 + tid] + red[384 + tid];
        size_t o = (size_t)bh * L_ + i0 + tid;
        if (half) g_RS1[o] = r; else g_RS0[o] = r;
        if ((it >> 3) == half) g_SD[o] = sdArr[tid];
    }
}

// ---------------- Kernel 3: O projection, fused diag-combine + diag*V -----------
__global__ __launch_bounds__(256, 2)
void gemm_out_bf16(const float* __restrict__ Wo, const float* __restrict__ bo,
                   float* __restrict__ out)
{
    __shared__ __nv_bfloat16 Ab[2][128*KP];
    __shared__ __nv_bfloat16 Wb[2][128*KP];

    const int m0 = blockIdx.y * 128, n0 = blockIdx.x * 128;
    const int tid = threadIdx.x, lane = tid & 31, w = tid >> 5;
    const int wr = w >> 1, wc = w & 1, g = lane >> 2, qd = lane & 3;
    const int rr = tid >> 3;
    const int c4 = (tid & 7) * 4;

    const int bq = m0 >> 11, l0 = m0 & (L_ - 1);

    float4 ra[4], rw[4];
    float dgv[4];
    auto ldg_chunk = [&](int kc) {
        int h = kc >> 1;
        size_t hrow = (size_t)(bq*NH + h) * L_ + l0;
        const float* Ag = g_V + hrow * D_ + (kc & 1)*32;
        const float* Wg = Wo + (size_t)n0 * H_ + kc*32;
        #pragma unroll
        for (int i = 0; i < 4; i++) {
            int r = i*32 + rr;
            ra[i]  = *(const float4*)&Ag[(size_t)r * D_ + c4];
            rw[i]  = *(const float4*)&Wg[(size_t)r * H_ + c4];
            dgv[i] = fast_exp2(g_SD[hrow + r]) * fast_rcp(g_RS0[hrow + r] + g_RS1[hrow + r]);
        }
    };
    auto sts_chunk = [&](int buf) {
        #pragma unroll
        for (int i = 0; i < 4; i++) {
            int r = i*32 + rr;
            float d = dgv[i];
            __nv_bfloat162* pa = (__nv_bfloat162*)(Ab[buf] + r*KP + c4);
            pa[0] = cvt2(ra[i].x*d, ra[i].y*d);
            pa[1] = cvt2(ra[i].z*d, ra[i].w*d);
            __nv_bfloat162* pw = (__nv_bfloat162*)(Wb[buf] + r*KP + c4);
            pw[0] = cvt2(rw[i].x, rw[i].y);
            pw[1] = cvt2(rw[i].z, rw[i].w);
        }
    };

    uint32_t qaA[2], wbaA[2];
    #pragma unroll
    for (int b = 0; b < 2; b++) {
        qaA[b]  = smem_u32(Ab[b] + (wr*32 + (lane & 15))*KP + ((lane >> 4) & 1)*8);
        wbaA[b] = smem_u32(Wb[b] + (wc*64 + ((lane >> 4) & 1)*8 + (lane & 7))*KP
                           + ((lane >> 3) & 1)*8);
    }

    float acc[2][8][4] = {};

    ldg_chunk(0);
    sts_chunk(0);
    ldg_chunk(1);

    for (int kc = 0; kc < 16; kc++) {
        int cur = kc & 1;
        __syncthreads();
        #pragma unroll
        for (int kk = 0; kk < 2; kk++) {
            uint32_t a0[4], a1[4];
            ldsm_x4(a0, qaA[cur] + kk*32);
            ldsm_x4(a1, qaA[cur] + 16*KP*2 + kk*32);
            #pragma unroll
            for (int p = 0; p < 4; p++) {
                uint32_t bb[4];
                ldsm_x4(bb, wbaA[cur] + p*(16*KP*2) + kk*32);
                mma16816(acc[0][2*p+0], a0, bb[0], bb[1]);
                mma16816(acc[0][2*p+1], a0, bb[2], bb[3]);
                mma16816(acc[1][2*p+0], a1, bb[0], bb[1]);
                mma16816(acc[1][2*p+1], a1, bb[2], bb[3]);
            }
        }
        if (kc < 15) {
            sts_chunk(cur ^ 1);
            if (kc < 14) ldg_chunk(kc + 2);
        }
    }

    #pragma unroll
    for (int mf = 0; mf < 2; mf++) {
        int rg = m0 + wr*32 + mf*16 + g;
        #pragma unroll
        for (int nf = 0; nf < 8; nf++) {
            int n = n0 + wc*64 + nf*8 + qd*2;
            float b0 = bo[n], b1 = bo[n+1];
            *(float2*)(out + (size_t)rg * H_ + n) =
                make_float2(acc[mf][nf][0] + b0, acc[mf][nf][1] + b1);
            *(float2*)(out + (size_t)(rg + 8) * H_ + n) =
                make_float2(acc[mf][nf][2] + b0, acc[mf][nf][3] + b1);
        }
    }
}

// ---------------- launch --------------------------------------------------------
extern "C" void kernel_launch(void* const* d_in, const int* in_sizes, int n_in,
                              void* d_out, int out_size)
{
    const float* q_in = (const float*)d_in[0];
    const float* k_in = (const float*)d_in[1];
    const float* v_in = (const float*)d_in[2];
    const float* Wq_w = (const float*)d_in[3];
    const float* Wq_b = (const float*)d_in[4];
    const float* Wk_w = (const float*)d_in[5];
    const float* Wk_b = (const float*)d_in[6];
    const float* Wv_w = (const float*)d_in[7];
    const float* Wv_b = (const float*)d_in[8];
    const float* Wo_w = (const float*)d_in[9];
    const float* Wo_b = (const float*)d_in[10];
    const float* Wp_w = (const float*)d_in[11];
    const float* Wp_b = (const float*)d_in[12];

    cudaFuncSetAttribute(attn_mma_kernel,
                         cudaFuncAttributeMaxDynamicSharedMemorySize, ATT_SMEM);
    cudaFuncSetAttribute(gemm_qkv_bf16,
                         cudaFuncAttributeMaxDynamicSharedMemorySize, QKV_SMEM);

    convert_kernel<<<13312, 256>>>(q_in, k_in, v_in, Wq_w, Wk_w, Wv_w, Wp_w);

    gemm_qkv_bf16<<<dim3(H_/128, (B_*L_)/128, 3), 256, QKV_SMEM>>>(Wq_b, Wk_b, Wv_b);

    attn_mma_kernel<<<dim3(L_/128, B_*NH, 2), 512, ATT_SMEM>>>(Wp_b);

    gemm_out_bf16<<<dim3(H_/128, (B_*L_)/128), 256>>>(Wo_w, Wo_b, (float*)d_out);
}